// round 4
// baseline (speedup 1.0000x reference)
#include <cuda_runtime.h>
#include <cuda_bf16.h>
#include <math.h>
#include <stdint.h>

// Problem constants
#define BB 2
#define SS 2048
#define DD 1024
#define HH 16
#define DK 64
#define MM (BB*SS)   // 4096 rows

typedef __nv_bfloat16 bf16;

// ---------------------------------------------------------------------------
// Device-global scratch (allocation-free)
// ---------------------------------------------------------------------------
__device__ float g_Q[MM*DD];
__device__ float g_K[MM*DD];
__device__ float g_V[MM*DD];
__device__ float g_A[MM*DD];
__device__ bf16 g_XH[MM*DD];
__device__ bf16 g_XL[MM*DD];
__device__ bf16 g_WTH[4*DD*DD];   // transposed weights hi [n][k]
__device__ bf16 g_WTL[4*DD*DD];   // transposed weights lo [n][k]

__device__ __forceinline__ uint32_t smem_u32(const void* p) {
    uint32_t a;
    asm("{ .reg .u64 t; cvta.to.shared.u64 t, %1; cvt.u32.u64 %0, t; }"
        : "=r"(a) : "l"(p));
    return a;
}

__device__ __forceinline__ void ldsm_x4(uint32_t* r, uint32_t addr) {
    asm volatile("ldmatrix.sync.aligned.m8n8.x4.shared.b16 {%0,%1,%2,%3}, [%4];"
                 : "=r"(r[0]), "=r"(r[1]), "=r"(r[2]), "=r"(r[3]) : "r"(addr));
}

__device__ __forceinline__ void mma16816(float* d, const uint32_t* a,
                                         uint32_t b0, uint32_t b1) {
    asm volatile(
        "mma.sync.aligned.m16n8k16.row.col.f32.bf16.bf16.f32 "
        "{%0,%1,%2,%3}, {%4,%5,%6,%7}, {%8,%9}, {%0,%1,%2,%3};"
        : "+f"(d[0]), "+f"(d[1]), "+f"(d[2]), "+f"(d[3])
        : "r"(a[0]), "r"(a[1]), "r"(a[2]), "r"(a[3]), "r"(b0), "r"(b1));
}

// ---------------------------------------------------------------------------
// fp32 -> bf16 hi/lo split
// ---------------------------------------------------------------------------
__global__ __launch_bounds__(256) void fsplit(
    const float* __restrict__ src, bf16* __restrict__ h, bf16* __restrict__ l, int n4)
{
    int i = blockIdx.x * 256 + threadIdx.x;
    if (i >= n4) return;
    float4 v = ((const float4*)src)[i];
    bf16 h0 = __float2bfloat16(v.x);
    bf16 h1 = __float2bfloat16(v.y);
    bf16 h2 = __float2bfloat16(v.z);
    bf16 h3 = __float2bfloat16(v.w);
    __nv_bfloat162 hh0; hh0.x = h0; hh0.y = h1;
    __nv_bfloat162 hh1; hh1.x = h2; hh1.y = h3;
    ((__nv_bfloat162*)h)[i*2]   = hh0;
    ((__nv_bfloat162*)h)[i*2+1] = hh1;
    __nv_bfloat162 ll0, ll1;
    ll0.x = __float2bfloat16(v.x - __bfloat162float(h0));
    ll0.y = __float2bfloat16(v.y - __bfloat162float(h1));
    ll1.x = __float2bfloat16(v.z - __bfloat162float(h2));
    ll1.y = __float2bfloat16(v.w - __bfloat162float(h3));
    ((__nv_bfloat162*)l)[i*2]   = ll0;
    ((__nv_bfloat162*)l)[i*2+1] = ll1;
}

// ---------------------------------------------------------------------------
// Weight transpose + split: W[k][n] fp32 -> T{h,l}[n][k] bf16
// ---------------------------------------------------------------------------
__global__ __launch_bounds__(256) void wtrans(
    const float* __restrict__ W, bf16* __restrict__ Th, bf16* __restrict__ Tl)
{
    __shared__ float t[32][33];
    const int tx = threadIdx.x, ty = threadIdx.y;   // (32, 8)
    const int bx = blockIdx.x * 32, by = blockIdx.y * 32;
#pragma unroll
    for (int i = 0; i < 4; i++)
        t[ty + i*8][tx] = W[(size_t)(by + ty + i*8) * DD + bx + tx];
    __syncthreads();
#pragma unroll
    for (int i = 0; i < 4; i++) {
        float v = t[tx][ty + i*8];
        size_t o = (size_t)(bx + ty + i*8) * DD + by + tx;
        bf16 h = __float2bfloat16(v);
        Th[o] = h;
        Tl[o] = __float2bfloat16(v - __bfloat162float(h));
    }
}

// ---------------------------------------------------------------------------
// bf16x3 GEMM via mma.sync: C[4096,1024] = A * B^T  (B given as [n][k])
// CTA 128x128, 8 warps (2x4), warp tile 64x32, K-chunk 64.
// smem: 4 tiles of 128x64 bf16 (16KB each), XOR-swizzled 16B chunks.
// ---------------------------------------------------------------------------
#define SM_AH 0
#define SM_AL 16384
#define SM_BH 32768
#define SM_BL 49152
#define GSMEM 65536

__global__ __launch_bounds__(256) void gemm_mma(
    const bf16* __restrict__ Ah, const bf16* __restrict__ Al,
    const bf16* __restrict__ Bh, const bf16* __restrict__ Bl,
    float* __restrict__ C)
{
    extern __shared__ char sm[];
    const uint32_t sb = smem_u32(sm);

    const int tid  = threadIdx.x;
    const int wid  = tid >> 5;
    const int lane = tid & 31;
    const int m0 = blockIdx.y * 128;
    const int n0 = blockIdx.x * 128;
    const int wm = (wid & 1) * 64;    // warp row offset in tile
    const int wn = (wid >> 1) * 32;   // warp col offset in tile

    float acc[4][4][4];
#pragma unroll
    for (int i = 0; i < 4; i++)
#pragma unroll
        for (int j = 0; j < 4; j++)
#pragma unroll
            for (int k = 0; k < 4; k++) acc[i][j][k] = 0.f;

    // gmem->smem geometry: thread loads 4 16B chunks per tile
    const int lrow = tid >> 1;            // 0..127
    const int lc0  = (tid & 1) * 4;       // chunk 0..3 or 4..7

    // ldmatrix lane addressing (A and B identical pattern)
    const int lrow16 = lane & 15;
    const int lhi    = lane >> 4;         // 0/1 selects k half (8 bf16 = 1 chunk)

    for (int kc = 0; kc < DD / 64; kc++) {
        const int k0 = kc * 64;
        const size_t gA = (size_t)(m0 + lrow) * DD + k0;
        const size_t gB = (size_t)(n0 + lrow) * DD + k0;
#pragma unroll
        for (int c = 0; c < 4; c++) {
            const int cc = lc0 + c;
            const uint32_t so = lrow * 128 + ((cc ^ (lrow & 7)) * 16);
            *(float4*)(sm + SM_AH + so) = *(const float4*)(Ah + gA + cc * 8);
            *(float4*)(sm + SM_AL + so) = *(const float4*)(Al + gA + cc * 8);
            *(float4*)(sm + SM_BH + so) = *(const float4*)(Bh + gB + cc * 8);
            *(float4*)(sm + SM_BL + so) = *(const float4*)(Bl + gB + cc * 8);
        }
        __syncthreads();

#pragma unroll
        for (int ks = 0; ks < 4; ks++) {
            const int chunk = ks * 2 + lhi;

            // fragment addresses for this k-step
            uint32_t aaddr[4], baddr[2];
#pragma unroll
            for (int mt = 0; mt < 4; mt++) {
                const int r = wm + mt * 16 + lrow16;
                aaddr[mt] = sb + r * 128 + ((chunk ^ (r & 7)) * 16);
            }
#pragma unroll
            for (int nt = 0; nt < 2; nt++) {
                const int r = wn + nt * 16 + lrow16;
                baddr[nt] = sb + r * 128 + ((chunk ^ (r & 7)) * 16);
            }

            uint32_t a[4][4], b[2][4];

            // term 1: Ah * Bh
#pragma unroll
            for (int mt = 0; mt < 4; mt++) ldsm_x4(a[mt], aaddr[mt] + SM_AH);
#pragma unroll
            for (int nt = 0; nt < 2; nt++) ldsm_x4(b[nt], baddr[nt] + SM_BH);
#pragma unroll
            for (int mt = 0; mt < 4; mt++)
#pragma unroll
                for (int nt = 0; nt < 4; nt++)
                    mma16816(acc[mt][nt], a[mt],
                             b[nt >> 1][nt & 1], b[nt >> 1][(nt & 1) + 2]);

            // term 2: Al * Bh (reuse b)
#pragma unroll
            for (int mt = 0; mt < 4; mt++) ldsm_x4(a[mt], aaddr[mt] + SM_AL);
#pragma unroll
            for (int mt = 0; mt < 4; mt++)
#pragma unroll
                for (int nt = 0; nt < 4; nt++)
                    mma16816(acc[mt][nt], a[mt],
                             b[nt >> 1][nt & 1], b[nt >> 1][(nt & 1) + 2]);

            // term 3: Ah * Bl
#pragma unroll
            for (int mt = 0; mt < 4; mt++) ldsm_x4(a[mt], aaddr[mt] + SM_AH);
#pragma unroll
            for (int nt = 0; nt < 2; nt++) ldsm_x4(b[nt], baddr[nt] + SM_BL);
#pragma unroll
            for (int mt = 0; mt < 4; mt++)
#pragma unroll
                for (int nt = 0; nt < 4; nt++)
                    mma16816(acc[mt][nt], a[mt],
                             b[nt >> 1][nt & 1], b[nt >> 1][(nt & 1) + 2]);
        }
        __syncthreads();
    }

    // Epilogue: direct fp32 stores (float2 per fragment pair)
    const int er = lane >> 2;          // 0..7
    const int ec = (lane & 3) * 2;     // 0,2,4,6
#pragma unroll
    for (int mt = 0; mt < 4; mt++) {
#pragma unroll
        for (int nt = 0; nt < 4; nt++) {
            float* p0 = C + (size_t)(m0 + wm + mt*16 + er) * DD + n0 + wn + nt*8 + ec;
            float* p1 = p0 + 8 * DD;
            float2 v0; v0.x = acc[mt][nt][0]; v0.y = acc[mt][nt][1];
            float2 v1; v1.x = acc[mt][nt][2]; v1.y = acc[mt][nt][3];
            *(float2*)p0 = v0;
            *(float2*)p1 = v1;
        }
    }
}

// ---------------------------------------------------------------------------
// Causal flash attention, fp32, 2 threads per query (each owns 32 of 64 dims).
// ---------------------------------------------------------------------------
#define FBM 128
#define FBN 32

__global__ __launch_bounds__(256, 2) void flash_attn2()
{
    __shared__ float Kb[FBN][DK];
    __shared__ float Vb[FBN][DK];

    const int tid  = threadIdx.x;
    const int qi   = tid >> 1;
    const int half = tid & 1;
    const int qb   = blockIdx.x;
    const int bh   = blockIdx.y;
    const int b    = bh / HH;
    const int h    = bh % HH;

    const int row = qb * FBM + qi;
    const float* qptr = g_Q + ((size_t)(b * SS + row)) * DD + h * DK + half * 32;

    float q[32];
#pragma unroll
    for (int i = 0; i < 8; i++) {
        float4 v = ((const float4*)qptr)[i];
        q[4*i+0] = v.x; q[4*i+1] = v.y; q[4*i+2] = v.z; q[4*i+3] = v.w;
    }

    float acc[32];
#pragma unroll
    for (int d = 0; d < 32; d++) acc[d] = 0.f;
    float m = -INFINITY;
    float l = 0.f;

    const int kend = qb * FBM + FBM;

    for (int ks = 0; ks < kend; ks += FBN) {
        for (int idx = tid; idx < FBN * (DK / 4); idx += 256) {
            const int r = idx >> 4;
            const int c = idx & 15;
            const size_t g = ((size_t)(b * SS + ks + r)) * DD + h * DK;
            ((float4*)&Kb[r][0])[c] = ((const float4*)(g_K + g))[c];
            ((float4*)&Vb[r][0])[c] = ((const float4*)(g_V + g))[c];
        }
        __syncthreads();

        float s[FBN];
#pragma unroll 4
        for (int j = 0; j < FBN; j++) {
            float a0 = 0.f, a1 = 0.f;
            const float4* kr = (const float4*)&Kb[j][half * 32];
#pragma unroll
            for (int d4 = 0; d4 < 4; d4++) {
                float4 kv = kr[d4];
                a0 = fmaf(q[4*d4+0], kv.x, a0);
                a0 = fmaf(q[4*d4+1], kv.y, a0);
                a0 = fmaf(q[4*d4+2], kv.z, a0);
                a0 = fmaf(q[4*d4+3], kv.w, a0);
            }
#pragma unroll
            for (int d4 = 4; d4 < 8; d4++) {
                float4 kv = kr[d4];
                a1 = fmaf(q[4*d4+0], kv.x, a1);
                a1 = fmaf(q[4*d4+1], kv.y, a1);
                a1 = fmaf(q[4*d4+2], kv.z, a1);
                a1 = fmaf(q[4*d4+3], kv.w, a1);
            }
            s[j] = a0 + a1;
        }
#pragma unroll
        for (int j = 0; j < FBN; j++) {
            float p = s[j] + __shfl_xor_sync(0xFFFFFFFFu, s[j], 1);
            s[j] = (ks + j <= row) ? p * 0.125f : -INFINITY;
        }

        float bmax = s[0];
#pragma unroll
        for (int j = 1; j < FBN; j++) bmax = fmaxf(bmax, s[j]);

        const float mn = fmaxf(m, bmax);
        const float corr = __expf(m - mn);
        l *= corr;
#pragma unroll
        for (int d = 0; d < 32; d++) acc[d] *= corr;

#pragma unroll 2
        for (int j = 0; j < FBN; j++) {
            const float p = __expf(s[j] - mn);
            l += p;
            const float4* vr = (const float4*)&Vb[j][half * 32];
#pragma unroll
            for (int d4 = 0; d4 < 8; d4++) {
                float4 vv = vr[d4];
                acc[4*d4+0] = fmaf(p, vv.x, acc[4*d4+0]);
                acc[4*d4+1] = fmaf(p, vv.y, acc[4*d4+1]);
                acc[4*d4+2] = fmaf(p, vv.z, acc[4*d4+2]);
                acc[4*d4+3] = fmaf(p, vv.w, acc[4*d4+3]);
            }
        }
        m = mn;
        __syncthreads();
    }

    const float inv = 1.f / l;
    float* op = g_A + ((size_t)(b * SS + row)) * DD + h * DK + half * 32;
#pragma unroll
    for (int d4 = 0; d4 < 8; d4++) {
        float4 v;
        v.x = acc[4*d4+0] * inv;
        v.y = acc[4*d4+1] * inv;
        v.z = acc[4*d4+2] * inv;
        v.w = acc[4*d4+3] * inv;
        ((float4*)op)[d4] = v;
    }
}

// ---------------------------------------------------------------------------
extern "C" void kernel_launch(void* const* d_in, const int* in_sizes, int n_in,
                              void* d_out, int out_size)
{
    const float* x  = (const float*)d_in[0];
    const float* Wq = (const float*)d_in[1];
    const float* Wk = (const float*)d_in[2];
    const float* Wv = (const float*)d_in[3];
    const float* Wo = (const float*)d_in[4];
    float* out = (float*)d_out;

    float *Qp, *Kp, *Vp, *Ap;
    bf16 *XH, *XL, *WTH, *WTL;
    cudaGetSymbolAddress((void**)&Qp, g_Q);
    cudaGetSymbolAddress((void**)&Kp, g_K);
    cudaGetSymbolAddress((void**)&Vp, g_V);
    cudaGetSymbolAddress((void**)&Ap, g_A);
    cudaGetSymbolAddress((void**)&XH, g_XH);
    cudaGetSymbolAddress((void**)&XL, g_XL);
    cudaGetSymbolAddress((void**)&WTH, g_WTH);
    cudaGetSymbolAddress((void**)&WTL, g_WTL);

    cudaFuncSetAttribute(gemm_mma,
                         cudaFuncAttributeMaxDynamicSharedMemorySize, GSMEM);

    dim3 tb(32, 8), tg(DD / 32, DD / 32);
    wtrans<<<tg, tb>>>(Wq, WTH + 0,                WTL + 0);
    wtrans<<<tg, tb>>>(Wk, WTH + 1*(size_t)DD*DD,  WTL + 1*(size_t)DD*DD);
    wtrans<<<tg, tb>>>(Wv, WTH + 2*(size_t)DD*DD,  WTL + 2*(size_t)DD*DD);
    wtrans<<<tg, tb>>>(Wo, WTH + 3*(size_t)DD*DD,  WTL + 3*(size_t)DD*DD);

    const int n4 = MM * DD / 4;
    fsplit<<<n4 / 256, 256>>>(x, XH, XL, n4);

    dim3 gg(DD / 128, MM / 128);   // (8, 32)
    gemm_mma<<<gg, 256, GSMEM>>>(XH, XL, WTH + 0,               WTL + 0,               Qp);
    gemm_mma<<<gg, 256, GSMEM>>>(XH, XL, WTH + 1*(size_t)DD*DD, WTL + 1*(size_t)DD*DD, Kp);
    gemm_mma<<<gg, 256, GSMEM>>>(XH, XL, WTH + 2*(size_t)DD*DD, WTL + 2*(size_t)DD*DD, Vp);

    flash_attn2<<<dim3(SS / FBM, BB * HH), 256>>>();

    fsplit<<<n4 / 256, 256>>>(Ap, XH, XL, n4);
    gemm_mma<<<gg, 256, GSMEM>>>(XH, XL, WTH + 3*(size_t)DD*DD, WTL + 3*(size_t)DD*DD, out);
}

// round 5
// speedup vs baseline: 1.0675x; 1.0675x over previous
#include <cuda_runtime.h>
#include <cuda_bf16.h>
#include <math.h>
#include <stdint.h>

// Problem constants
#define BB 2
#define SS 2048
#define DD 1024
#define HH 16
#define DK 64
#define MM (BB*SS)   // 4096 rows

typedef __nv_bfloat16 bf16;

// ---------------------------------------------------------------------------
// Device-global scratch (allocation-free)
// ---------------------------------------------------------------------------
__device__ float g_Q[MM*DD];
__device__ float g_K[MM*DD];
__device__ float g_V[MM*DD];
__device__ float g_A[MM*DD];
__device__ bf16 g_XH[MM*DD];
__device__ bf16 g_XL[MM*DD];
__device__ bf16 g_WTH[4*DD*DD];   // transposed weights hi [n][k]
__device__ bf16 g_WTL[4*DD*DD];   // transposed weights lo [n][k]

__device__ __forceinline__ uint32_t smem_u32(const void* p) {
    uint32_t a;
    asm("{ .reg .u64 t; cvta.to.shared.u64 t, %1; cvt.u32.u64 %0, t; }"
        : "=r"(a) : "l"(p));
    return a;
}

__device__ __forceinline__ void ldsm_x4(uint32_t* r, uint32_t addr) {
    asm volatile("ldmatrix.sync.aligned.m8n8.x4.shared.b16 {%0,%1,%2,%3}, [%4];"
                 : "=r"(r[0]), "=r"(r[1]), "=r"(r[2]), "=r"(r[3]) : "r"(addr));
}

__device__ __forceinline__ void mma16816(float* d, const uint32_t* a,
                                         uint32_t b0, uint32_t b1) {
    asm volatile(
        "mma.sync.aligned.m16n8k16.row.col.f32.bf16.bf16.f32 "
        "{%0,%1,%2,%3}, {%4,%5,%6,%7}, {%8,%9}, {%0,%1,%2,%3};"
        : "+f"(d[0]), "+f"(d[1]), "+f"(d[2]), "+f"(d[3])
        : "r"(a[0]), "r"(a[1]), "r"(a[2]), "r"(a[3]), "r"(b0), "r"(b1));
}

// ---------------------------------------------------------------------------
// fp32 -> bf16 hi/lo split
// ---------------------------------------------------------------------------
__global__ __launch_bounds__(256) void fsplit(
    const float* __restrict__ src, bf16* __restrict__ h, bf16* __restrict__ l, int n4)
{
    int i = blockIdx.x * 256 + threadIdx.x;
    if (i >= n4) return;
    float4 v = ((const float4*)src)[i];
    bf16 h0 = __float2bfloat16(v.x);
    bf16 h1 = __float2bfloat16(v.y);
    bf16 h2 = __float2bfloat16(v.z);
    bf16 h3 = __float2bfloat16(v.w);
    __nv_bfloat162 hh0; hh0.x = h0; hh0.y = h1;
    __nv_bfloat162 hh1; hh1.x = h2; hh1.y = h3;
    ((__nv_bfloat162*)h)[i*2]   = hh0;
    ((__nv_bfloat162*)h)[i*2+1] = hh1;
    __nv_bfloat162 ll0, ll1;
    ll0.x = __float2bfloat16(v.x - __bfloat162float(h0));
    ll0.y = __float2bfloat16(v.y - __bfloat162float(h1));
    ll1.x = __float2bfloat16(v.z - __bfloat162float(h2));
    ll1.y = __float2bfloat16(v.w - __bfloat162float(h3));
    ((__nv_bfloat162*)l)[i*2]   = ll0;
    ((__nv_bfloat162*)l)[i*2+1] = ll1;
}

// ---------------------------------------------------------------------------
// Weight transpose + split: W[k][n] fp32 -> T{h,l}[n][k] bf16
// ---------------------------------------------------------------------------
__global__ __launch_bounds__(256) void wtrans(
    const float* __restrict__ W, bf16* __restrict__ Th, bf16* __restrict__ Tl)
{
    __shared__ float t[32][33];
    const int tx = threadIdx.x, ty = threadIdx.y;   // (32, 8)
    const int bx = blockIdx.x * 32, by = blockIdx.y * 32;
#pragma unroll
    for (int i = 0; i < 4; i++)
        t[ty + i*8][tx] = W[(size_t)(by + ty + i*8) * DD + bx + tx];
    __syncthreads();
#pragma unroll
    for (int i = 0; i < 4; i++) {
        float v = t[tx][ty + i*8];
        size_t o = (size_t)(bx + ty + i*8) * DD + by + tx;
        bf16 h = __float2bfloat16(v);
        Th[o] = h;
        Tl[o] = __float2bfloat16(v - __bfloat162float(h));
    }
}

// ---------------------------------------------------------------------------
// bf16x3 GEMM via mma.sync: C[4096,1024] = A * B^T  (B given as [n][k])
// CTA 128x128, 8 warps (2x4), warp tile 64x32, K-chunk 64.
// ---------------------------------------------------------------------------
#define SM_AH 0
#define SM_AL 16384
#define SM_BH 32768
#define SM_BL 49152
#define GSMEM 65536

__global__ __launch_bounds__(256) void gemm_mma(
    const bf16* __restrict__ Ah, const bf16* __restrict__ Al,
    const bf16* __restrict__ Bh, const bf16* __restrict__ Bl,
    float* __restrict__ C)
{
    extern __shared__ char sm[];
    const uint32_t sb = smem_u32(sm);

    const int tid  = threadIdx.x;
    const int wid  = tid >> 5;
    const int lane = tid & 31;
    const int m0 = blockIdx.y * 128;
    const int n0 = blockIdx.x * 128;
    const int wm = (wid & 1) * 64;
    const int wn = (wid >> 1) * 32;

    float acc[4][4][4];
#pragma unroll
    for (int i = 0; i < 4; i++)
#pragma unroll
        for (int j = 0; j < 4; j++)
#pragma unroll
            for (int k = 0; k < 4; k++) acc[i][j][k] = 0.f;

    const int lrow = tid >> 1;
    const int lc0  = (tid & 1) * 4;

    const int lrow16 = lane & 15;
    const int lhi    = lane >> 4;

    for (int kc = 0; kc < DD / 64; kc++) {
        const int k0 = kc * 64;
        const size_t gA = (size_t)(m0 + lrow) * DD + k0;
        const size_t gB = (size_t)(n0 + lrow) * DD + k0;
#pragma unroll
        for (int c = 0; c < 4; c++) {
            const int cc = lc0 + c;
            const uint32_t so = lrow * 128 + ((cc ^ (lrow & 7)) * 16);
            *(float4*)(sm + SM_AH + so) = *(const float4*)(Ah + gA + cc * 8);
            *(float4*)(sm + SM_AL + so) = *(const float4*)(Al + gA + cc * 8);
            *(float4*)(sm + SM_BH + so) = *(const float4*)(Bh + gB + cc * 8);
            *(float4*)(sm + SM_BL + so) = *(const float4*)(Bl + gB + cc * 8);
        }
        __syncthreads();

#pragma unroll
        for (int ks = 0; ks < 4; ks++) {
            const int chunk = ks * 2 + lhi;

            uint32_t aaddr[4], baddr[2];
#pragma unroll
            for (int mt = 0; mt < 4; mt++) {
                const int r = wm + mt * 16 + lrow16;
                aaddr[mt] = sb + r * 128 + ((chunk ^ (r & 7)) * 16);
            }
#pragma unroll
            for (int nt = 0; nt < 2; nt++) {
                const int r = wn + nt * 16 + lrow16;
                baddr[nt] = sb + r * 128 + ((chunk ^ (r & 7)) * 16);
            }

            uint32_t a[4][4], b[2][4];

#pragma unroll
            for (int mt = 0; mt < 4; mt++) ldsm_x4(a[mt], aaddr[mt] + SM_AH);
#pragma unroll
            for (int nt = 0; nt < 2; nt++) ldsm_x4(b[nt], baddr[nt] + SM_BH);
#pragma unroll
            for (int mt = 0; mt < 4; mt++)
#pragma unroll
                for (int nt = 0; nt < 4; nt++)
                    mma16816(acc[mt][nt], a[mt],
                             b[nt >> 1][nt & 1], b[nt >> 1][(nt & 1) + 2]);

#pragma unroll
            for (int mt = 0; mt < 4; mt++) ldsm_x4(a[mt], aaddr[mt] + SM_AL);
#pragma unroll
            for (int mt = 0; mt < 4; mt++)
#pragma unroll
                for (int nt = 0; nt < 4; nt++)
                    mma16816(acc[mt][nt], a[mt],
                             b[nt >> 1][nt & 1], b[nt >> 1][(nt & 1) + 2]);

#pragma unroll
            for (int mt = 0; mt < 4; mt++) ldsm_x4(a[mt], aaddr[mt] + SM_AH);
#pragma unroll
            for (int nt = 0; nt < 2; nt++) ldsm_x4(b[nt], baddr[nt] + SM_BL);
#pragma unroll
            for (int mt = 0; mt < 4; mt++)
#pragma unroll
                for (int nt = 0; nt < 4; nt++)
                    mma16816(acc[mt][nt], a[mt],
                             b[nt >> 1][nt & 1], b[nt >> 1][(nt & 1) + 2]);
        }
        __syncthreads();
    }

    const int er = lane >> 2;
    const int ec = (lane & 3) * 2;
#pragma unroll
    for (int mt = 0; mt < 4; mt++) {
#pragma unroll
        for (int nt = 0; nt < 4; nt++) {
            float* p0 = C + (size_t)(m0 + wm + mt*16 + er) * DD + n0 + wn + nt*8 + ec;
            float* p1 = p0 + 8 * DD;
            float2 v0; v0.x = acc[mt][nt][0]; v0.y = acc[mt][nt][1];
            float2 v1; v1.x = acc[mt][nt][2]; v1.y = acc[mt][nt][3];
            *(float2*)p0 = v0;
            *(float2*)p1 = v1;
        }
    }
}

// ---------------------------------------------------------------------------
// Causal flash attention, fp32, 2 threads per query (32 dims each).
// FBN=16 so live state (q[32]+acc[32]+s[16]) fits in registers WITHOUT spill.
// ---------------------------------------------------------------------------
#define FBM 128
#define FBN 16

__global__ __launch_bounds__(256) void flash_attn2()
{
    __shared__ float Kb[FBN][DK];
    __shared__ float Vb[FBN][DK];

    const int tid  = threadIdx.x;
    const int qi   = tid >> 1;
    const int half = tid & 1;
    const int qb   = blockIdx.x;
    const int bh   = blockIdx.y;
    const int b    = bh / HH;
    const int h    = bh % HH;

    const int row = qb * FBM + qi;
    const float* qptr = g_Q + ((size_t)(b * SS + row)) * DD + h * DK + half * 32;

    float q[32];
#pragma unroll
    for (int i = 0; i < 8; i++) {
        float4 v = ((const float4*)qptr)[i];
        q[4*i+0] = v.x; q[4*i+1] = v.y; q[4*i+2] = v.z; q[4*i+3] = v.w;
    }

    float acc[32];
#pragma unroll
    for (int d = 0; d < 32; d++) acc[d] = 0.f;
    float m = -INFINITY;
    float l = 0.f;

    const int kend = qb * FBM + FBM;

    for (int ks = 0; ks < kend; ks += FBN) {
        // 16 rows x 16 float4 = 256 slots: exactly one per thread
        {
            const int r = tid >> 4;
            const int c = tid & 15;
            const size_t g = ((size_t)(b * SS + ks + r)) * DD + h * DK;
            ((float4*)&Kb[r][0])[c] = ((const float4*)(g_K + g))[c];
            ((float4*)&Vb[r][0])[c] = ((const float4*)(g_V + g))[c];
        }
        __syncthreads();

        float s[FBN];
#pragma unroll
        for (int j = 0; j < FBN; j++) {
            float a0 = 0.f, a1 = 0.f;
            const float4* kr = (const float4*)&Kb[j][half * 32];
#pragma unroll
            for (int d4 = 0; d4 < 4; d4++) {
                float4 kv = kr[d4];
                a0 = fmaf(q[4*d4+0], kv.x, a0);
                a0 = fmaf(q[4*d4+1], kv.y, a0);
                a0 = fmaf(q[4*d4+2], kv.z, a0);
                a0 = fmaf(q[4*d4+3], kv.w, a0);
            }
#pragma unroll
            for (int d4 = 4; d4 < 8; d4++) {
                float4 kv = kr[d4];
                a1 = fmaf(q[4*d4+0], kv.x, a1);
                a1 = fmaf(q[4*d4+1], kv.y, a1);
                a1 = fmaf(q[4*d4+2], kv.z, a1);
                a1 = fmaf(q[4*d4+3], kv.w, a1);
            }
            s[j] = a0 + a1;
        }
#pragma unroll
        for (int j = 0; j < FBN; j++) {
            float p = s[j] + __shfl_xor_sync(0xFFFFFFFFu, s[j], 1);
            s[j] = (ks + j <= row) ? p * 0.125f : -INFINITY;
        }

        float bmax = s[0];
#pragma unroll
        for (int j = 1; j < FBN; j++) bmax = fmaxf(bmax, s[j]);

        const float mn = fmaxf(m, bmax);
        const float corr = __expf(m - mn);
        l *= corr;
#pragma unroll
        for (int d = 0; d < 32; d++) acc[d] *= corr;

#pragma unroll
        for (int j = 0; j < FBN; j++) {
            const float p = __expf(s[j] - mn);
            l += p;
            const float4* vr = (const float4*)&Vb[j][half * 32];
#pragma unroll
            for (int d4 = 0; d4 < 8; d4++) {
                float4 vv = vr[d4];
                acc[4*d4+0] = fmaf(p, vv.x, acc[4*d4+0]);
                acc[4*d4+1] = fmaf(p, vv.y, acc[4*d4+1]);
                acc[4*d4+2] = fmaf(p, vv.z, acc[4*d4+2]);
                acc[4*d4+3] = fmaf(p, vv.w, acc[4*d4+3]);
            }
        }
        m = mn;
        __syncthreads();
    }

    const float inv = 1.f / l;
    float* op = g_A + ((size_t)(b * SS + row)) * DD + h * DK + half * 32;
#pragma unroll
    for (int d4 = 0; d4 < 8; d4++) {
        float4 v;
        v.x = acc[4*d4+0] * inv;
        v.y = acc[4*d4+1] * inv;
        v.z = acc[4*d4+2] * inv;
        v.w = acc[4*d4+3] * inv;
        ((float4*)op)[d4] = v;
    }
}

// ---------------------------------------------------------------------------
extern "C" void kernel_launch(void* const* d_in, const int* in_sizes, int n_in,
                              void* d_out, int out_size)
{
    const float* x  = (const float*)d_in[0];
    const float* Wq = (const float*)d_in[1];
    const float* Wk = (const float*)d_in[2];
    const float* Wv = (const float*)d_in[3];
    const float* Wo = (const float*)d_in[4];
    float* out = (float*)d_out;

    float *Qp, *Kp, *Vp, *Ap;
    bf16 *XH, *XL, *WTH, *WTL;
    cudaGetSymbolAddress((void**)&Qp, g_Q);
    cudaGetSymbolAddress((void**)&Kp, g_K);
    cudaGetSymbolAddress((void**)&Vp, g_V);
    cudaGetSymbolAddress((void**)&Ap, g_A);
    cudaGetSymbolAddress((void**)&XH, g_XH);
    cudaGetSymbolAddress((void**)&XL, g_XL);
    cudaGetSymbolAddress((void**)&WTH, g_WTH);
    cudaGetSymbolAddress((void**)&WTL, g_WTL);

    cudaFuncSetAttribute(gemm_mma,
                         cudaFuncAttributeMaxDynamicSharedMemorySize, GSMEM);

    dim3 tb(32, 8), tg(DD / 32, DD / 32);
    wtrans<<<tg, tb>>>(Wq, WTH + 0,                WTL + 0);
    wtrans<<<tg, tb>>>(Wk, WTH + 1*(size_t)DD*DD,  WTL + 1*(size_t)DD*DD);
    wtrans<<<tg, tb>>>(Wv, WTH + 2*(size_t)DD*DD,  WTL + 2*(size_t)DD*DD);
    wtrans<<<tg, tb>>>(Wo, WTH + 3*(size_t)DD*DD,  WTL + 3*(size_t)DD*DD);

    const int n4 = MM * DD / 4;
    fsplit<<<n4 / 256, 256>>>(x, XH, XL, n4);

    dim3 gg(DD / 128, MM / 128);   // (8, 32)
    gemm_mma<<<gg, 256, GSMEM>>>(XH, XL, WTH + 0,               WTL + 0,               Qp);
    gemm_mma<<<gg, 256, GSMEM>>>(XH, XL, WTH + 1*(size_t)DD*DD, WTL + 1*(size_t)DD*DD, Kp);
    gemm_mma<<<gg, 256, GSMEM>>>(XH, XL, WTH + 2*(size_t)DD*DD, WTL + 2*(size_t)DD*DD, Vp);

    flash_attn2<<<dim3(SS / FBM, BB * HH), 256>>>();

    fsplit<<<n4 / 256, 256>>>(Ap, XH, XL, n4);
    gemm_mma<<<gg, 256, GSMEM>>>(XH, XL, WTH + 3*(size_t)DD*DD, WTL + 3*(size_t)DD*DD, out);
}

// round 8
// speedup vs baseline: 2.9903x; 2.8011x over previous
#include <cuda_runtime.h>
#include <cuda_bf16.h>
#include <math.h>
#include <stdint.h>

#define BB 2
#define SS 2048
#define DD 1024
#define HH 16
#define DK 64
#define MM (BB*SS)   // 4096 rows

typedef __nv_bfloat16 bf16;

// ---------------------------------------------------------------------------
// Device-global scratch (allocation-free)
// ---------------------------------------------------------------------------
__device__ bf16 g_XH[MM*DD];
__device__ bf16 g_XL[MM*DD];
__device__ bf16 g_WTH[4*DD*DD];    // transposed weights hi [n][k]
__device__ bf16 g_WTL[4*DD*DD];    // transposed weights lo [n][k]
__device__ bf16 g_QH[MM*DD];
__device__ bf16 g_QL[MM*DD];
__device__ bf16 g_KH[MM*DD];
__device__ bf16 g_KL[MM*DD];
__device__ bf16 g_VH[MM*DD];
__device__ bf16 g_VL[MM*DD];
__device__ bf16 g_VTH[MM*DD];      // [b][d][s]
__device__ bf16 g_VTL[MM*DD];
__device__ bf16 g_AH[MM*DD];       // attention out hi/lo
__device__ bf16 g_AL[MM*DD];

__device__ __forceinline__ uint32_t smem_u32(const void* p) {
    uint32_t a;
    asm("{ .reg .u64 t; cvta.to.shared.u64 t, %1; cvt.u32.u64 %0, t; }"
        : "=r"(a) : "l"(p));
    return a;
}

__device__ __forceinline__ void ldsm_x4(uint32_t* r, uint32_t addr) {
    asm volatile("ldmatrix.sync.aligned.m8n8.x4.shared.b16 {%0,%1,%2,%3}, [%4];"
                 : "=r"(r[0]), "=r"(r[1]), "=r"(r[2]), "=r"(r[3]) : "r"(addr));
}

__device__ __forceinline__ void mma16816(float* d, const uint32_t* a,
                                         uint32_t b0, uint32_t b1) {
    asm volatile(
        "mma.sync.aligned.m16n8k16.row.col.f32.bf16.bf16.f32 "
        "{%0,%1,%2,%3}, {%4,%5,%6,%7}, {%8,%9}, {%0,%1,%2,%3};"
        : "+f"(d[0]), "+f"(d[1]), "+f"(d[2]), "+f"(d[3])
        : "r"(a[0]), "r"(a[1]), "r"(a[2]), "r"(a[3]), "r"(b0), "r"(b1));
}

// pack two fp32 -> bf16x2 (lo, hi)
__device__ __forceinline__ uint32_t cvt2(float lo, float hi) {
    uint32_t r;
    asm("cvt.rn.bf16x2.f32 %0, %1, %2;" : "=r"(r) : "f"(hi), "f"(lo));
    return r;
}

// ---------------------------------------------------------------------------
// fp32 -> bf16 hi/lo split
// ---------------------------------------------------------------------------
__global__ __launch_bounds__(256) void fsplit(
    const float* __restrict__ src, bf16* __restrict__ h, bf16* __restrict__ l, int n4)
{
    int i = blockIdx.x * 256 + threadIdx.x;
    if (i >= n4) return;
    float4 v = ((const float4*)src)[i];
    bf16 h0 = __float2bfloat16(v.x);
    bf16 h1 = __float2bfloat16(v.y);
    bf16 h2 = __float2bfloat16(v.z);
    bf16 h3 = __float2bfloat16(v.w);
    __nv_bfloat162 hh0; hh0.x = h0; hh0.y = h1;
    __nv_bfloat162 hh1; hh1.x = h2; hh1.y = h3;
    ((__nv_bfloat162*)h)[i*2]   = hh0;
    ((__nv_bfloat162*)h)[i*2+1] = hh1;
    __nv_bfloat162 ll0, ll1;
    ll0.x = __float2bfloat16(v.x - __bfloat162float(h0));
    ll0.y = __float2bfloat16(v.y - __bfloat162float(h1));
    ll1.x = __float2bfloat16(v.z - __bfloat162float(h2));
    ll1.y = __float2bfloat16(v.w - __bfloat162float(h3));
    ((__nv_bfloat162*)l)[i*2]   = ll0;
    ((__nv_bfloat162*)l)[i*2+1] = ll1;
}

// ---------------------------------------------------------------------------
// Weight transpose + split: W[k][n] fp32 -> T{h,l}[n][k] bf16
// ---------------------------------------------------------------------------
__global__ __launch_bounds__(256) void wtrans(
    const float* __restrict__ W, bf16* __restrict__ Th, bf16* __restrict__ Tl)
{
    __shared__ float t[32][33];
    const int tx = threadIdx.x, ty = threadIdx.y;   // (32, 8)
    const int bx = blockIdx.x * 32, by = blockIdx.y * 32;
#pragma unroll
    for (int i = 0; i < 4; i++)
        t[ty + i*8][tx] = W[(size_t)(by + ty + i*8) * DD + bx + tx];
    __syncthreads();
#pragma unroll
    for (int i = 0; i < 4; i++) {
        float v = t[tx][ty + i*8];
        size_t o = (size_t)(bx + ty + i*8) * DD + by + tx;
        bf16 h = __float2bfloat16(v);
        Th[o] = h;
        Tl[o] = __float2bfloat16(v - __bfloat162float(h));
    }
}

// ---------------------------------------------------------------------------
// bf16 transpose: V[b*S+s][d] -> VT[(b*D+d)][s]  (both hi and lo arrays)
// ---------------------------------------------------------------------------
__global__ __launch_bounds__(256) void vtrans()
{
    __shared__ bf16 th[32][34];
    __shared__ bf16 tl[32][34];
    const int tx = threadIdx.x, ty = threadIdx.y;   // (32, 8)
    const int d0 = blockIdx.x * 32;
    const int s0 = blockIdx.y * 32;
    const int b  = blockIdx.z;
#pragma unroll
    for (int i = 0; i < 4; i++) {
        const size_t g = (size_t)(b*SS + s0 + ty + i*8) * DD + d0 + tx;
        th[ty + i*8][tx] = g_VH[g];
        tl[ty + i*8][tx] = g_VL[g];
    }
    __syncthreads();
#pragma unroll
    for (int i = 0; i < 4; i++) {
        const size_t g = (size_t)(b*DD + d0 + ty + i*8) * SS + s0 + tx;
        g_VTH[g] = th[tx][ty + i*8];
        g_VTL[g] = tl[tx][ty + i*8];
    }
}

// ---------------------------------------------------------------------------
// bf16x3 GEMM via mma.sync: C[4096,1024] = A * B^T  (B given as [n][k])
// CTA 128x128, 8 warps, warp tile 64x32, K-chunk 64.
// Epilogue: fp32 C (BF16OUT=false) or bf16 hi/lo split (BF16OUT=true).
// ---------------------------------------------------------------------------
#define SM_AH 0
#define SM_AL 16384
#define SM_BH 32768
#define SM_BL 49152
#define GSMEM 65536

template<bool BF16OUT>
__global__ __launch_bounds__(256) void gemm_mma(
    const bf16* __restrict__ Ah, const bf16* __restrict__ Al,
    const bf16* __restrict__ Bh, const bf16* __restrict__ Bl,
    float* __restrict__ C, bf16* __restrict__ CH, bf16* __restrict__ CL)
{
    extern __shared__ char sm[];
    const uint32_t sb = smem_u32(sm);

    const int tid  = threadIdx.x;
    const int wid  = tid >> 5;
    const int lane = tid & 31;
    const int m0 = blockIdx.y * 128;
    const int n0 = blockIdx.x * 128;
    const int wm = (wid & 1) * 64;
    const int wn = (wid >> 1) * 32;

    float acc[4][4][4];
#pragma unroll
    for (int i = 0; i < 4; i++)
#pragma unroll
        for (int j = 0; j < 4; j++)
#pragma unroll
            for (int k = 0; k < 4; k++) acc[i][j][k] = 0.f;

    const int lrow = tid >> 1;
    const int lc0  = (tid & 1) * 4;
    const int lrow16 = lane & 15;
    const int lhi    = lane >> 4;

    for (int kc = 0; kc < DD / 64; kc++) {
        const int k0 = kc * 64;
        const size_t gA = (size_t)(m0 + lrow) * DD + k0;
        const size_t gB = (size_t)(n0 + lrow) * DD + k0;
#pragma unroll
        for (int c = 0; c < 4; c++) {
            const int cc = lc0 + c;
            const uint32_t so = lrow * 128 + ((cc ^ (lrow & 7)) * 16);
            *(float4*)(sm + SM_AH + so) = *(const float4*)(Ah + gA + cc * 8);
            *(float4*)(sm + SM_AL + so) = *(const float4*)(Al + gA + cc * 8);
            *(float4*)(sm + SM_BH + so) = *(const float4*)(Bh + gB + cc * 8);
            *(float4*)(sm + SM_BL + so) = *(const float4*)(Bl + gB + cc * 8);
        }
        __syncthreads();

#pragma unroll
        for (int ks = 0; ks < 4; ks++) {
            const int chunk = ks * 2 + lhi;

            uint32_t aaddr[4], baddr[2];
#pragma unroll
            for (int mt = 0; mt < 4; mt++) {
                const int r = wm + mt * 16 + lrow16;
                aaddr[mt] = sb + r * 128 + ((chunk ^ (r & 7)) * 16);
            }
#pragma unroll
            for (int nt = 0; nt < 2; nt++) {
                const int r = wn + nt * 16 + lrow16;
                baddr[nt] = sb + r * 128 + ((chunk ^ (r & 7)) * 16);
            }

            uint32_t a[4][4], b[2][4];

#pragma unroll
            for (int mt = 0; mt < 4; mt++) ldsm_x4(a[mt], aaddr[mt] + SM_AH);
#pragma unroll
            for (int nt = 0; nt < 2; nt++) ldsm_x4(b[nt], baddr[nt] + SM_BH);
#pragma unroll
            for (int mt = 0; mt < 4; mt++)
#pragma unroll
                for (int nt = 0; nt < 4; nt++)
                    mma16816(acc[mt][nt], a[mt],
                             b[nt >> 1][nt & 1], b[nt >> 1][(nt & 1) + 2]);

#pragma unroll
            for (int mt = 0; mt < 4; mt++) ldsm_x4(a[mt], aaddr[mt] + SM_AL);
#pragma unroll
            for (int mt = 0; mt < 4; mt++)
#pragma unroll
                for (int nt = 0; nt < 4; nt++)
                    mma16816(acc[mt][nt], a[mt],
                             b[nt >> 1][nt & 1], b[nt >> 1][(nt & 1) + 2]);

#pragma unroll
            for (int mt = 0; mt < 4; mt++) ldsm_x4(a[mt], aaddr[mt] + SM_AH);
#pragma unroll
            for (int nt = 0; nt < 2; nt++) ldsm_x4(b[nt], baddr[nt] + SM_BL);
#pragma unroll
            for (int mt = 0; mt < 4; mt++)
#pragma unroll
                for (int nt = 0; nt < 4; nt++)
                    mma16816(acc[mt][nt], a[mt],
                             b[nt >> 1][nt & 1], b[nt >> 1][(nt & 1) + 2]);
        }
        __syncthreads();
    }

    const int er = lane >> 2;
    const int ec = (lane & 3) * 2;
#pragma unroll
    for (int mt = 0; mt < 4; mt++) {
#pragma unroll
        for (int nt = 0; nt < 4; nt++) {
            const size_t o0 = (size_t)(m0 + wm + mt*16 + er) * DD + n0 + wn + nt*8 + ec;
            const size_t o1 = o0 + 8 * DD;
            if (BF16OUT) {
                float v0 = acc[mt][nt][0], v1 = acc[mt][nt][1];
                float v2 = acc[mt][nt][2], v3 = acc[mt][nt][3];
                bf16 h0 = __float2bfloat16(v0), h1 = __float2bfloat16(v1);
                bf16 h2 = __float2bfloat16(v2), h3 = __float2bfloat16(v3);
                __nv_bfloat162 hp0; hp0.x = h0; hp0.y = h1;
                __nv_bfloat162 hp1; hp1.x = h2; hp1.y = h3;
                *(__nv_bfloat162*)(CH + o0) = hp0;
                *(__nv_bfloat162*)(CH + o1) = hp1;
                __nv_bfloat162 lp0, lp1;
                lp0.x = __float2bfloat16(v0 - __bfloat162float(h0));
                lp0.y = __float2bfloat16(v1 - __bfloat162float(h1));
                lp1.x = __float2bfloat16(v2 - __bfloat162float(h2));
                lp1.y = __float2bfloat16(v3 - __bfloat162float(h3));
                *(__nv_bfloat162*)(CL + o0) = lp0;
                *(__nv_bfloat162*)(CL + o1) = lp1;
            } else {
                float2 v0; v0.x = acc[mt][nt][0]; v0.y = acc[mt][nt][1];
                float2 v1; v1.x = acc[mt][nt][2]; v1.y = acc[mt][nt][3];
                *(float2*)(C + o0) = v0;
                *(float2*)(C + o1) = v1;
            }
        }
    }
}

// ---------------------------------------------------------------------------
// Tensor-core causal flash attention (bf16x3 QK^T and PV, no-max softmax).
// CTA: 128 threads (4 warps), 64 queries x DK=64. Key blocks of 64.
// smem tiles 64x64 bf16, 128B rows, XOR-swizzled like gemm_mma.
// ---------------------------------------------------------------------------
#define FS_KH 0
#define FS_KL 8192
#define FS_VH 16384
#define FS_VL 24576

__global__ __launch_bounds__(128) void flash_mma()
{
    __shared__ char sm[32768];
    const uint32_t sb = smem_u32(sm);

    const int tid  = threadIdx.x;
    const int w    = tid >> 5;
    const int lane = tid & 31;
    const int bh = blockIdx.x;
    const int b  = bh >> 4;
    const int h  = bh & 15;
    const int qb = blockIdx.y;

    const int lrow16 = lane & 15;
    const int lhi    = lane >> 4;

    // ---- stage Q tile (64x64 hi+lo) into smem (reusing K region) ----
    {
        const bf16* QHg = g_QH + (size_t)(b*SS + qb*64) * DD + h*64;
        const bf16* QLg = g_QL + (size_t)(b*SS + qb*64) * DD + h*64;
#pragma unroll
        for (int i = 0; i < 4; i++) {
            const int idx = tid + i*128;
            const int r = idx >> 3, c = idx & 7;
            const uint32_t so = r * 128 + ((c ^ (r & 7)) * 16);
            *(float4*)(sm + FS_KH + so) = *(const float4*)(QHg + (size_t)r*DD + c*8);
            *(float4*)(sm + FS_KL + so) = *(const float4*)(QLg + (size_t)r*DD + c*8);
        }
    }
    __syncthreads();

    // ---- preload Q fragments (4 k-steps, hi+lo) ----
    uint32_t qh[4][4], ql[4][4];
#pragma unroll
    for (int kk = 0; kk < 4; kk++) {
        const int r = w*16 + lrow16;
        const int ch = kk*2 + lhi;
        const uint32_t ao = r * 128 + ((ch ^ (r & 7)) * 16);
        ldsm_x4(qh[kk], sb + FS_KH + ao);
        ldsm_x4(ql[kk], sb + FS_KL + ao);
    }
    __syncthreads();

    float oacc[8][4];
#pragma unroll
    for (int j = 0; j < 8; j++)
#pragma unroll
        for (int e = 0; e < 4; e++) oacc[j][e] = 0.f;
    float l0 = 0.f, l1 = 0.f;

    const int rloc = w*16 + (lane >> 2);       // local query row (0..63)
    const int grow = qb*64 + rloc;             // seq position of query row 0
    const int ecol = (lane & 3) * 2;

    for (int kb = 0; kb <= qb; kb++) {
        // ---- stage K and VT tiles ----
        {
            const bf16* KHg  = g_KH  + (size_t)(b*SS + kb*64) * DD + h*64;
            const bf16* KLg  = g_KL  + (size_t)(b*SS + kb*64) * DD + h*64;
            const bf16* VTHg = g_VTH + (size_t)(b*DD + h*64) * SS + kb*64;
            const bf16* VTLg = g_VTL + (size_t)(b*DD + h*64) * SS + kb*64;
#pragma unroll
            for (int i = 0; i < 4; i++) {
                const int idx = tid + i*128;
                const int r = idx >> 3, c = idx & 7;
                const uint32_t so = r * 128 + ((c ^ (r & 7)) * 16);
                *(float4*)(sm + FS_KH + so) = *(const float4*)(KHg  + (size_t)r*DD + c*8);
                *(float4*)(sm + FS_KL + so) = *(const float4*)(KLg  + (size_t)r*DD + c*8);
                *(float4*)(sm + FS_VH + so) = *(const float4*)(VTHg + (size_t)r*SS + c*8);
                *(float4*)(sm + FS_VL + so) = *(const float4*)(VTLg + (size_t)r*SS + c*8);
            }
        }
        __syncthreads();

        // ---- S = Q K^T (bf16x3) ----
        float sacc[8][4];
#pragma unroll
        for (int j = 0; j < 8; j++)
#pragma unroll
            for (int e = 0; e < 4; e++) sacc[j][e] = 0.f;

#pragma unroll
        for (int kk = 0; kk < 4; kk++) {
            const int ch = kk*2 + lhi;
#pragma unroll
            for (int nb = 0; nb < 4; nb++) {
                const int r = nb*16 + lrow16;
                const uint32_t ao = r * 128 + ((ch ^ (r & 7)) * 16);
                uint32_t bhf[4], blf[4];
                ldsm_x4(bhf, sb + FS_KH + ao);
                ldsm_x4(blf, sb + FS_KL + ao);
#pragma unroll
                for (int nt = 0; nt < 2; nt++) {
                    float* s = sacc[nb*2 + nt];
                    mma16816(s, qh[kk], bhf[nt], bhf[nt + 2]);
                    mma16816(s, qh[kk], blf[nt], blf[nt + 2]);
                    mma16816(s, ql[kk], bhf[nt], bhf[nt + 2]);
                }
            }
        }

        // ---- softmax (no max subtraction): p = exp(s/8), masked causal ----
        if (kb == qb) {
#pragma unroll
            for (int j = 0; j < 8; j++) {
#pragma unroll
                for (int e = 0; e < 4; e++) {
                    const int col = kb*64 + j*8 + ecol + (e & 1);
                    const int row = grow + ((e >> 1) * 8);
                    float p = (col <= row) ? __expf(sacc[j][e] * 0.125f) : 0.f;
                    sacc[j][e] = p;
                    if (e < 2) l0 += p; else l1 += p;
                }
            }
        } else {
#pragma unroll
            for (int j = 0; j < 8; j++) {
#pragma unroll
                for (int e = 0; e < 4; e++) {
                    float p = __expf(sacc[j][e] * 0.125f);
                    sacc[j][e] = p;
                    if (e < 2) l0 += p; else l1 += p;
                }
            }
        }

        // ---- O += P V (bf16x3) ----
#pragma unroll
        for (int kk = 0; kk < 4; kk++) {
            // build P fragments for this 16-key step
            uint32_t pah[4], pal[4];
            {
                const float* s0 = sacc[kk*2];
                const float* s1 = sacc[kk*2 + 1];
                float h00 = __bfloat162float(__float2bfloat16(s0[0]));
                float h01 = __bfloat162float(__float2bfloat16(s0[1]));
                float h02 = __bfloat162float(__float2bfloat16(s0[2]));
                float h03 = __bfloat162float(__float2bfloat16(s0[3]));
                float h10 = __bfloat162float(__float2bfloat16(s1[0]));
                float h11 = __bfloat162float(__float2bfloat16(s1[1]));
                float h12 = __bfloat162float(__float2bfloat16(s1[2]));
                float h13 = __bfloat162float(__float2bfloat16(s1[3]));
                pah[0] = cvt2(h00, h01);
                pah[1] = cvt2(h02, h03);
                pah[2] = cvt2(h10, h11);
                pah[3] = cvt2(h12, h13);
                pal[0] = cvt2(s0[0] - h00, s0[1] - h01);
                pal[1] = cvt2(s0[2] - h02, s0[3] - h03);
                pal[2] = cvt2(s1[0] - h10, s1[1] - h11);
                pal[3] = cvt2(s1[2] - h12, s1[3] - h13);
            }
            const int ch = kk*2 + lhi;
#pragma unroll
            for (int db = 0; db < 4; db++) {
                const int r = db*16 + lrow16;
                const uint32_t ao = r * 128 + ((ch ^ (r & 7)) * 16);
                uint32_t vhf[4], vlf[4];
                ldsm_x4(vhf, sb + FS_VH + ao);
                ldsm_x4(vlf, sb + FS_VL + ao);
#pragma unroll
                for (int nt = 0; nt < 2; nt++) {
                    float* o = oacc[db*2 + nt];
                    mma16816(o, pah, vhf[nt], vhf[nt + 2]);
                    mma16816(o, pal, vhf[nt], vhf[nt + 2]);
                    mma16816(o, pah, vlf[nt], vlf[nt + 2]);
                }
            }
        }
        __syncthreads();
    }

    // ---- finalize: cross-lane l reduce, divide, split, store ----
    l0 += __shfl_xor_sync(0xFFFFFFFFu, l0, 1);
    l0 += __shfl_xor_sync(0xFFFFFFFFu, l0, 2);
    l1 += __shfl_xor_sync(0xFFFFFFFFu, l1, 1);
    l1 += __shfl_xor_sync(0xFFFFFFFFu, l1, 2);
    const float inv0 = 1.f / l0;
    const float inv1 = 1.f / l1;

    const size_t tok0 = (size_t)(b*SS + grow) * DD + h*64;
    const size_t tok1 = tok0 + 8 * DD;
#pragma unroll
    for (int j = 0; j < 8; j++) {
        const int col = j*8 + ecol;
        float v0 = oacc[j][0] * inv0;
        float v1 = oacc[j][1] * inv0;
        float v2 = oacc[j][2] * inv1;
        float v3 = oacc[j][3] * inv1;
        bf16 h0 = __float2bfloat16(v0), h1 = __float2bfloat16(v1);
        bf16 h2 = __float2bfloat16(v2), h3 = __float2bfloat16(v3);
        __nv_bfloat162 hp0; hp0.x = h0; hp0.y = h1;
        __nv_bfloat162 hp1; hp1.x = h2; hp1.y = h3;
        *(__nv_bfloat162*)(g_AH + tok0 + col) = hp0;
        *(__nv_bfloat162*)(g_AH + tok1 + col) = hp1;
        __nv_bfloat162 lp0, lp1;
        lp0.x = __float2bfloat16(v0 - __bfloat162float(h0));
        lp0.y = __float2bfloat16(v1 - __bfloat162float(h1));
        lp1.x = __float2bfloat16(v2 - __bfloat162float(h2));
        lp1.y = __float2bfloat16(v3 - __bfloat162float(h3));
        *(__nv_bfloat162*)(g_AL + tok0 + col) = lp0;
        *(__nv_bfloat162*)(g_AL + tok1 + col) = lp1;
    }
}

// ---------------------------------------------------------------------------
extern "C" void kernel_launch(void* const* d_in, const int* in_sizes, int n_in,
                              void* d_out, int out_size)
{
    const float* x  = (const float*)d_in[0];
    const float* Wq = (const float*)d_in[1];
    const float* Wk = (const float*)d_in[2];
    const float* Wv = (const float*)d_in[3];
    const float* Wo = (const float*)d_in[4];
    float* out = (float*)d_out;

    bf16 *XH, *XL, *WTH, *WTL, *QH, *QL, *KH, *KL, *VH, *VL, *AH, *AL;
    cudaGetSymbolAddress((void**)&XH, g_XH);
    cudaGetSymbolAddress((void**)&XL, g_XL);
    cudaGetSymbolAddress((void**)&WTH, g_WTH);
    cudaGetSymbolAddress((void**)&WTL, g_WTL);
    cudaGetSymbolAddress((void**)&QH, g_QH);
    cudaGetSymbolAddress((void**)&QL, g_QL);
    cudaGetSymbolAddress((void**)&KH, g_KH);
    cudaGetSymbolAddress((void**)&KL, g_KL);
    cudaGetSymbolAddress((void**)&VH, g_VH);
    cudaGetSymbolAddress((void**)&VL, g_VL);
    cudaGetSymbolAddress((void**)&AH, g_AH);
    cudaGetSymbolAddress((void**)&AL, g_AL);

    cudaFuncSetAttribute(gemm_mma<true>,
                         cudaFuncAttributeMaxDynamicSharedMemorySize, GSMEM);
    cudaFuncSetAttribute(gemm_mma<false>,
                         cudaFuncAttributeMaxDynamicSharedMemorySize, GSMEM);

    dim3 tb(32, 8), tg(DD / 32, DD / 32);
    wtrans<<<tg, tb>>>(Wq, WTH + 0,                WTL + 0);
    wtrans<<<tg, tb>>>(Wk, WTH + 1*(size_t)DD*DD,  WTL + 1*(size_t)DD*DD);
    wtrans<<<tg, tb>>>(Wv, WTH + 2*(size_t)DD*DD,  WTL + 2*(size_t)DD*DD);
    wtrans<<<tg, tb>>>(Wo, WTH + 3*(size_t)DD*DD,  WTL + 3*(size_t)DD*DD);

    const int n4 = MM * DD / 4;
    fsplit<<<n4 / 256, 256>>>(x, XH, XL, n4);

    dim3 gg(DD / 128, MM / 128);   // (8, 32)
    gemm_mma<true><<<gg, 256, GSMEM>>>(XH, XL, WTH + 0,               WTL + 0,               nullptr, QH, QL);
    gemm_mma<true><<<gg, 256, GSMEM>>>(XH, XL, WTH + 1*(size_t)DD*DD, WTL + 1*(size_t)DD*DD, nullptr, KH, KL);
    gemm_mma<true><<<gg, 256, GSMEM>>>(XH, XL, WTH + 2*(size_t)DD*DD, WTL + 2*(size_t)DD*DD, nullptr, VH, VL);

    vtrans<<<dim3(DD/32, SS/32, BB), tb>>>();

    flash_mma<<<dim3(BB*HH, SS/64), 128>>>();

    gemm_mma<false><<<gg, 256, GSMEM>>>(AH, AL, WTH + 3*(size_t)DD*DD, WTL + 3*(size_t)DD*DD, out, nullptr, nullptr);
}

// round 9
// speedup vs baseline: 3.1158x; 1.0420x over previous
#include <cuda_runtime.h>
#include <cuda_bf16.h>
#include <math.h>
#include <stdint.h>

#define BB 2
#define SS 2048
#define DD 1024
#define HH 16
#define DK 64
#define MM (BB*SS)   // 4096 rows

typedef __nv_bfloat16 bf16;

// ---------------------------------------------------------------------------
// Device-global scratch (allocation-free)
// ---------------------------------------------------------------------------
__device__ bf16 g_XH[MM*DD];
__device__ bf16 g_XL[MM*DD];
__device__ bf16 g_WTH[4*DD*DD];    // transposed weights hi [n][k]
__device__ bf16 g_WTL[4*DD*DD];    // transposed weights lo [n][k]
__device__ bf16 g_QH[MM*DD];
__device__ bf16 g_QL[MM*DD];
__device__ bf16 g_KH[MM*DD];
__device__ bf16 g_KL[MM*DD];
__device__ bf16 g_VH[MM*DD];
__device__ bf16 g_VL[MM*DD];
__device__ bf16 g_VTH[MM*DD];      // [b][d][s]
__device__ bf16 g_VTL[MM*DD];
__device__ bf16 g_AH[MM*DD];       // attention out hi/lo
__device__ bf16 g_AL[MM*DD];

__device__ __forceinline__ uint32_t smem_u32(const void* p) {
    uint32_t a;
    asm("{ .reg .u64 t; cvta.to.shared.u64 t, %1; cvt.u32.u64 %0, t; }"
        : "=r"(a) : "l"(p));
    return a;
}

__device__ __forceinline__ void ldsm_x4(uint32_t* r, uint32_t addr) {
    asm volatile("ldmatrix.sync.aligned.m8n8.x4.shared.b16 {%0,%1,%2,%3}, [%4];"
                 : "=r"(r[0]), "=r"(r[1]), "=r"(r[2]), "=r"(r[3]) : "r"(addr));
}

__device__ __forceinline__ void mma16816(float* d, const uint32_t* a,
                                         uint32_t b0, uint32_t b1) {
    asm volatile(
        "mma.sync.aligned.m16n8k16.row.col.f32.bf16.bf16.f32 "
        "{%0,%1,%2,%3}, {%4,%5,%6,%7}, {%8,%9}, {%0,%1,%2,%3};"
        : "+f"(d[0]), "+f"(d[1]), "+f"(d[2]), "+f"(d[3])
        : "r"(a[0]), "r"(a[1]), "r"(a[2]), "r"(a[3]), "r"(b0), "r"(b1));
}

__device__ __forceinline__ uint32_t cvt2(float lo, float hi) {
    uint32_t r;
    asm("cvt.rn.bf16x2.f32 %0, %1, %2;" : "=r"(r) : "f"(hi), "f"(lo));
    return r;
}

__device__ __forceinline__ void cpa16(uint32_t s, const void* g) {
    asm volatile("cp.async.cg.shared.global [%0], [%1], 16;" :: "r"(s), "l"(g));
}
__device__ __forceinline__ void cpcommit() {
    asm volatile("cp.async.commit_group;");
}
template<int N> __device__ __forceinline__ void cpwait() {
    asm volatile("cp.async.wait_group %0;" :: "n"(N));
}

// ---------------------------------------------------------------------------
// fp32 -> bf16 hi/lo split
// ---------------------------------------------------------------------------
__global__ __launch_bounds__(256) void fsplit(
    const float* __restrict__ src, bf16* __restrict__ h, bf16* __restrict__ l, int n4)
{
    int i = blockIdx.x * 256 + threadIdx.x;
    if (i >= n4) return;
    float4 v = ((const float4*)src)[i];
    bf16 h0 = __float2bfloat16(v.x);
    bf16 h1 = __float2bfloat16(v.y);
    bf16 h2 = __float2bfloat16(v.z);
    bf16 h3 = __float2bfloat16(v.w);
    __nv_bfloat162 hh0; hh0.x = h0; hh0.y = h1;
    __nv_bfloat162 hh1; hh1.x = h2; hh1.y = h3;
    ((__nv_bfloat162*)h)[i*2]   = hh0;
    ((__nv_bfloat162*)h)[i*2+1] = hh1;
    __nv_bfloat162 ll0, ll1;
    ll0.x = __float2bfloat16(v.x - __bfloat162float(h0));
    ll0.y = __float2bfloat16(v.y - __bfloat162float(h1));
    ll1.x = __float2bfloat16(v.z - __bfloat162float(h2));
    ll1.y = __float2bfloat16(v.w - __bfloat162float(h3));
    ((__nv_bfloat162*)l)[i*2]   = ll0;
    ((__nv_bfloat162*)l)[i*2+1] = ll1;
}

// ---------------------------------------------------------------------------
// Weight transpose + split: W[k][n] fp32 -> T{h,l}[n][k] bf16
// ---------------------------------------------------------------------------
__global__ __launch_bounds__(256) void wtrans(
    const float* __restrict__ W, bf16* __restrict__ Th, bf16* __restrict__ Tl)
{
    __shared__ float t[32][33];
    const int tx = threadIdx.x, ty = threadIdx.y;   // (32, 8)
    const int bx = blockIdx.x * 32, by = blockIdx.y * 32;
#pragma unroll
    for (int i = 0; i < 4; i++)
        t[ty + i*8][tx] = W[(size_t)(by + ty + i*8) * DD + bx + tx];
    __syncthreads();
#pragma unroll
    for (int i = 0; i < 4; i++) {
        float v = t[tx][ty + i*8];
        size_t o = (size_t)(bx + ty + i*8) * DD + by + tx;
        bf16 h = __float2bfloat16(v);
        Th[o] = h;
        Tl[o] = __float2bfloat16(v - __bfloat162float(h));
    }
}

// ---------------------------------------------------------------------------
// bf16 transpose: V[b*S+s][d] -> VT[(b*D+d)][s]
// ---------------------------------------------------------------------------
__global__ __launch_bounds__(256) void vtrans()
{
    __shared__ bf16 th[32][34];
    __shared__ bf16 tl[32][34];
    const int tx = threadIdx.x, ty = threadIdx.y;
    const int d0 = blockIdx.x * 32;
    const int s0 = blockIdx.y * 32;
    const int b  = blockIdx.z;
#pragma unroll
    for (int i = 0; i < 4; i++) {
        const size_t g = (size_t)(b*SS + s0 + ty + i*8) * DD + d0 + tx;
        th[ty + i*8][tx] = g_VH[g];
        tl[ty + i*8][tx] = g_VL[g];
    }
    __syncthreads();
#pragma unroll
    for (int i = 0; i < 4; i++) {
        const size_t g = (size_t)(b*DD + d0 + ty + i*8) * SS + s0 + tx;
        g_VTH[g] = th[tx][ty + i*8];
        g_VTL[g] = tl[tx][ty + i*8];
    }
}

// ---------------------------------------------------------------------------
// bf16x3 GEMM, cp.async 2-stage pipeline. CTA 128x128, K-chunk 32.
// SMEM tile layout: 128x32 bf16 packed as 64 rows x 128B:
//   logical (r, c) -> physical row (r & 63), chunk (c + 4*(r>>6)), XOR-swizzled.
// ---------------------------------------------------------------------------
#define G_STG 32768
#define T_AH 0
#define T_AL 8192
#define T_BH 16384
#define T_BL 24576
#define GSMEM (2*G_STG)

__device__ __forceinline__ uint32_t toff(int r, int c) {
    const int pr = r & 63;
    const int pc = c + ((r >> 6) << 2);
    return (uint32_t)(pr * 128 + ((pc ^ (pr & 7)) * 16));
}

template<bool BF16OUT>
__global__ __launch_bounds__(256) void gemm_mma(
    const bf16* __restrict__ Ah, const bf16* __restrict__ Al,
    const bf16* __restrict__ Bh, const bf16* __restrict__ Bl,
    float* __restrict__ C, bf16* __restrict__ CH, bf16* __restrict__ CL)
{
    extern __shared__ char sm[];
    const uint32_t sb = smem_u32(sm);

    const int tid  = threadIdx.x;
    const int wid  = tid >> 5;
    const int lane = tid & 31;
    const int m0 = blockIdx.y * 128;
    const int n0 = blockIdx.x * 128;
    const int wm = (wid & 1) * 64;
    const int wn = (wid >> 1) * 32;

    float acc[4][4][4];
#pragma unroll
    for (int i = 0; i < 4; i++)
#pragma unroll
        for (int j = 0; j < 4; j++)
#pragma unroll
            for (int k = 0; k < 4; k++) acc[i][j][k] = 0.f;

    // load geometry: thread covers row (tid>>1), chunks {cb, cb+1}
    const int lr = tid >> 1;
    const int cb = (tid & 1) * 2;
    const uint32_t so0 = toff(lr, cb);
    const uint32_t so1 = toff(lr, cb + 1);
    const bf16* pAh = Ah + (size_t)(m0 + lr) * DD + cb * 8;
    const bf16* pAl = Al + (size_t)(m0 + lr) * DD + cb * 8;
    const bf16* pBh = Bh + (size_t)(n0 + lr) * DD + cb * 8;
    const bf16* pBl = Bl + (size_t)(n0 + lr) * DD + cb * 8;

    const int lrow16 = lane & 15;
    const int lhi    = lane >> 4;

#define G_ISSUE(kc, st)                                                        \
    do {                                                                       \
        const int _k0 = (kc) * 32;                                             \
        const uint32_t _s = sb + (st) * G_STG;                                 \
        cpa16(_s + T_AH + so0, pAh + _k0);                                     \
        cpa16(_s + T_AH + so1, pAh + _k0 + 8);                                 \
        cpa16(_s + T_AL + so0, pAl + _k0);                                     \
        cpa16(_s + T_AL + so1, pAl + _k0 + 8);                                 \
        cpa16(_s + T_BH + so0, pBh + _k0);                                     \
        cpa16(_s + T_BH + so1, pBh + _k0 + 8);                                 \
        cpa16(_s + T_BL + so0, pBl + _k0);                                     \
        cpa16(_s + T_BL + so1, pBl + _k0 + 8);                                 \
    } while (0)

    G_ISSUE(0, 0);
    cpcommit();

    for (int kc = 0; kc < 32; kc++) {
        if (kc < 31) {
            G_ISSUE(kc + 1, (kc + 1) & 1);
            cpcommit();
            cpwait<1>();
        } else {
            cpwait<0>();
        }
        __syncthreads();

        const uint32_t st = sb + (kc & 1) * G_STG;
#pragma unroll
        for (int ks = 0; ks < 2; ks++) {
            const int ch = ks * 2 + lhi;

            uint32_t aaddr[4], baddr[2];
#pragma unroll
            for (int mt = 0; mt < 4; mt++)
                aaddr[mt] = st + toff(wm + mt * 16 + lrow16, ch);
#pragma unroll
            for (int nt = 0; nt < 2; nt++)
                baddr[nt] = st + toff(wn + nt * 16 + lrow16, ch);

            uint32_t a[4][4], b[2][4];

#pragma unroll
            for (int mt = 0; mt < 4; mt++) ldsm_x4(a[mt], aaddr[mt] + T_AH);
#pragma unroll
            for (int nt = 0; nt < 2; nt++) ldsm_x4(b[nt], baddr[nt] + T_BH);
#pragma unroll
            for (int mt = 0; mt < 4; mt++)
#pragma unroll
                for (int nt = 0; nt < 4; nt++)
                    mma16816(acc[mt][nt], a[mt],
                             b[nt >> 1][nt & 1], b[nt >> 1][(nt & 1) + 2]);

#pragma unroll
            for (int mt = 0; mt < 4; mt++) ldsm_x4(a[mt], aaddr[mt] + T_AL);
#pragma unroll
            for (int mt = 0; mt < 4; mt++)
#pragma unroll
                for (int nt = 0; nt < 4; nt++)
                    mma16816(acc[mt][nt], a[mt],
                             b[nt >> 1][nt & 1], b[nt >> 1][(nt & 1) + 2]);

#pragma unroll
            for (int mt = 0; mt < 4; mt++) ldsm_x4(a[mt], aaddr[mt] + T_AH);
#pragma unroll
            for (int nt = 0; nt < 2; nt++) ldsm_x4(b[nt], baddr[nt] + T_BL);
#pragma unroll
            for (int mt = 0; mt < 4; mt++)
#pragma unroll
                for (int nt = 0; nt < 4; nt++)
                    mma16816(acc[mt][nt], a[mt],
                             b[nt >> 1][nt & 1], b[nt >> 1][(nt & 1) + 2]);
        }
        __syncthreads();
    }
#undef G_ISSUE

    const int er = lane >> 2;
    const int ec = (lane & 3) * 2;
#pragma unroll
    for (int mt = 0; mt < 4; mt++) {
#pragma unroll
        for (int nt = 0; nt < 4; nt++) {
            const size_t o0 = (size_t)(m0 + wm + mt*16 + er) * DD + n0 + wn + nt*8 + ec;
            const size_t o1 = o0 + 8 * DD;
            if (BF16OUT) {
                float v0 = acc[mt][nt][0], v1 = acc[mt][nt][1];
                float v2 = acc[mt][nt][2], v3 = acc[mt][nt][3];
                bf16 h0 = __float2bfloat16(v0), h1 = __float2bfloat16(v1);
                bf16 h2 = __float2bfloat16(v2), h3 = __float2bfloat16(v3);
                __nv_bfloat162 hp0; hp0.x = h0; hp0.y = h1;
                __nv_bfloat162 hp1; hp1.x = h2; hp1.y = h3;
                *(__nv_bfloat162*)(CH + o0) = hp0;
                *(__nv_bfloat162*)(CH + o1) = hp1;
                __nv_bfloat162 lp0, lp1;
                lp0.x = __float2bfloat16(v0 - __bfloat162float(h0));
                lp0.y = __float2bfloat16(v1 - __bfloat162float(h1));
                lp1.x = __float2bfloat16(v2 - __bfloat162float(h2));
                lp1.y = __float2bfloat16(v3 - __bfloat162float(h3));
                *(__nv_bfloat162*)(CL + o0) = lp0;
                *(__nv_bfloat162*)(CL + o1) = lp1;
            } else {
                float2 v0; v0.x = acc[mt][nt][0]; v0.y = acc[mt][nt][1];
                float2 v1; v1.x = acc[mt][nt][2]; v1.y = acc[mt][nt][3];
                *(float2*)(C + o0) = v0;
                *(float2*)(C + o1) = v1;
            }
        }
    }
}

// ---------------------------------------------------------------------------
// Tensor-core causal flash attention, cp.async 2-stage K/V pipeline.
// CTA: 128 threads, 64 queries x DK=64. Tiles 64x64 bf16, 128B rows.
// ---------------------------------------------------------------------------
#define F_STG 32768
#define FS_KH 0
#define FS_KL 8192
#define FS_VH 16384
#define FS_VL 24576
#define FSMEM (2*F_STG)

__global__ __launch_bounds__(128) void flash_mma()
{
    extern __shared__ char fsm[];
    const uint32_t sb = smem_u32(fsm);

    const int tid  = threadIdx.x;
    const int w    = tid >> 5;
    const int lane = tid & 31;
    const int bh = blockIdx.x;
    const int b  = bh >> 4;
    const int h  = bh & 15;
    const int qb = blockIdx.y;

    const int lrow16 = lane & 15;
    const int lhi    = lane >> 4;

    // ---- stage Q tile (64x64 hi+lo) into stage-0 region ----
    {
        const bf16* QHg = g_QH + (size_t)(b*SS + qb*64) * DD + h*64;
        const bf16* QLg = g_QL + (size_t)(b*SS + qb*64) * DD + h*64;
#pragma unroll
        for (int i = 0; i < 4; i++) {
            const int idx = tid + i*128;
            const int r = idx >> 3, c = idx & 7;
            const uint32_t so = r * 128 + ((c ^ (r & 7)) * 16);
            *(float4*)(fsm + FS_KH + so) = *(const float4*)(QHg + (size_t)r*DD + c*8);
            *(float4*)(fsm + FS_KL + so) = *(const float4*)(QLg + (size_t)r*DD + c*8);
        }
    }
    __syncthreads();

    uint32_t qh[4][4], ql[4][4];
#pragma unroll
    for (int kk = 0; kk < 4; kk++) {
        const int r = w*16 + lrow16;
        const int ch = kk*2 + lhi;
        const uint32_t ao = r * 128 + ((ch ^ (r & 7)) * 16);
        ldsm_x4(qh[kk], sb + FS_KH + ao);
        ldsm_x4(ql[kk], sb + FS_KL + ao);
    }
    __syncthreads();

    // per-thread KV load geometry (4 chunks per tile)
    const int vr = tid >> 3;          // 0..15 base row
    const int vc = tid & 7;           // chunk
    const bf16* KHg  = g_KH  + (size_t)(b*SS) * DD + h*64;
    const bf16* KLg  = g_KL  + (size_t)(b*SS) * DD + h*64;
    const bf16* VTHg = g_VTH + (size_t)(b*DD + h*64) * SS;
    const bf16* VTLg = g_VTL + (size_t)(b*DD + h*64) * SS;

#define F_ISSUE(kb, st)                                                        \
    do {                                                                       \
        const uint32_t _s = sb + (st) * F_STG;                                 \
        const int _k0 = (kb) * 64;                                             \
        _Pragma("unroll")                                                      \
        for (int i = 0; i < 4; i++) {                                          \
            const int r = vr + i * 16;                                         \
            const uint32_t so = r * 128 + ((vc ^ (r & 7)) * 16);               \
            cpa16(_s + FS_KH + so, KHg  + (size_t)(_k0 + r)*DD + vc*8);        \
            cpa16(_s + FS_KL + so, KLg  + (size_t)(_k0 + r)*DD + vc*8);        \
            cpa16(_s + FS_VH + so, VTHg + (size_t)r*SS + _k0 + vc*8);          \
            cpa16(_s + FS_VL + so, VTLg + (size_t)r*SS + _k0 + vc*8);          \
        }                                                                      \
    } while (0)

    F_ISSUE(0, 0);
    cpcommit();

    float oacc[8][4];
#pragma unroll
    for (int j = 0; j < 8; j++)
#pragma unroll
        for (int e = 0; e < 4; e++) oacc[j][e] = 0.f;
    float l0 = 0.f, l1 = 0.f;

    const int rloc = w*16 + (lane >> 2);
    const int grow = qb*64 + rloc;
    const int ecol = (lane & 3) * 2;

    for (int kb = 0; kb <= qb; kb++) {
        if (kb < qb) {
            F_ISSUE(kb + 1, (kb + 1) & 1);
            cpcommit();
            cpwait<1>();
        } else {
            cpwait<0>();
        }
        __syncthreads();

        const uint32_t st = sb + (kb & 1) * F_STG;

        // ---- S = Q K^T (bf16x3) ----
        float sacc[8][4];
#pragma unroll
        for (int j = 0; j < 8; j++)
#pragma unroll
            for (int e = 0; e < 4; e++) sacc[j][e] = 0.f;

#pragma unroll
        for (int kk = 0; kk < 4; kk++) {
            const int ch = kk*2 + lhi;
#pragma unroll
            for (int nb = 0; nb < 4; nb++) {
                const int r = nb*16 + lrow16;
                const uint32_t ao = r * 128 + ((ch ^ (r & 7)) * 16);
                uint32_t bhf[4], blf[4];
                ldsm_x4(bhf, st + FS_KH + ao);
                ldsm_x4(blf, st + FS_KL + ao);
#pragma unroll
                for (int nt = 0; nt < 2; nt++) {
                    float* s = sacc[nb*2 + nt];
                    mma16816(s, qh[kk], bhf[nt], bhf[nt + 2]);
                    mma16816(s, qh[kk], blf[nt], blf[nt + 2]);
                    mma16816(s, ql[kk], bhf[nt], bhf[nt + 2]);
                }
            }
        }

        // ---- softmax (no-max): p = exp(s/8), causal masked ----
        if (kb == qb) {
#pragma unroll
            for (int j = 0; j < 8; j++) {
#pragma unroll
                for (int e = 0; e < 4; e++) {
                    const int col = kb*64 + j*8 + ecol + (e & 1);
                    const int row = grow + ((e >> 1) * 8);
                    float p = (col <= row) ? __expf(sacc[j][e] * 0.125f) : 0.f;
                    sacc[j][e] = p;
                    if (e < 2) l0 += p; else l1 += p;
                }
            }
        } else {
#pragma unroll
            for (int j = 0; j < 8; j++) {
#pragma unroll
                for (int e = 0; e < 4; e++) {
                    float p = __expf(sacc[j][e] * 0.125f);
                    sacc[j][e] = p;
                    if (e < 2) l0 += p; else l1 += p;
                }
            }
        }

        // ---- O += P V (bf16x3) ----
#pragma unroll
        for (int kk = 0; kk < 4; kk++) {
            uint32_t pah[4], pal[4];
            {
                const float* s0 = sacc[kk*2];
                const float* s1 = sacc[kk*2 + 1];
                float h00 = __bfloat162float(__float2bfloat16(s0[0]));
                float h01 = __bfloat162float(__float2bfloat16(s0[1]));
                float h02 = __bfloat162float(__float2bfloat16(s0[2]));
                float h03 = __bfloat162float(__float2bfloat16(s0[3]));
                float h10 = __bfloat162float(__float2bfloat16(s1[0]));
                float h11 = __bfloat162float(__float2bfloat16(s1[1]));
                float h12 = __bfloat162float(__float2bfloat16(s1[2]));
                float h13 = __bfloat162float(__float2bfloat16(s1[3]));
                pah[0] = cvt2(h00, h01);
                pah[1] = cvt2(h02, h03);
                pah[2] = cvt2(h10, h11);
                pah[3] = cvt2(h12, h13);
                pal[0] = cvt2(s0[0] - h00, s0[1] - h01);
                pal[1] = cvt2(s0[2] - h02, s0[3] - h03);
                pal[2] = cvt2(s1[0] - h10, s1[1] - h11);
                pal[3] = cvt2(s1[2] - h12, s1[3] - h13);
            }
            const int ch = kk*2 + lhi;
#pragma unroll
            for (int db = 0; db < 4; db++) {
                const int r = db*16 + lrow16;
                const uint32_t ao = r * 128 + ((ch ^ (r & 7)) * 16);
                uint32_t vhf[4], vlf[4];
                ldsm_x4(vhf, st + FS_VH + ao);
                ldsm_x4(vlf, st + FS_VL + ao);
#pragma unroll
                for (int nt = 0; nt < 2; nt++) {
                    float* o = oacc[db*2 + nt];
                    mma16816(o, pah, vhf[nt], vhf[nt + 2]);
                    mma16816(o, pal, vhf[nt], vhf[nt + 2]);
                    mma16816(o, pah, vlf[nt], vlf[nt + 2]);
                }
            }
        }
        __syncthreads();
    }
#undef F_ISSUE

    l0 += __shfl_xor_sync(0xFFFFFFFFu, l0, 1);
    l0 += __shfl_xor_sync(0xFFFFFFFFu, l0, 2);
    l1 += __shfl_xor_sync(0xFFFFFFFFu, l1, 1);
    l1 += __shfl_xor_sync(0xFFFFFFFFu, l1, 2);
    const float inv0 = 1.f / l0;
    const float inv1 = 1.f / l1;

    const size_t tok0 = (size_t)(b*SS + grow) * DD + h*64;
    const size_t tok1 = tok0 + 8 * DD;
#pragma unroll
    for (int j = 0; j < 8; j++) {
        const int col = j*8 + ecol;
        float v0 = oacc[j][0] * inv0;
        float v1 = oacc[j][1] * inv0;
        float v2 = oacc[j][2] * inv1;
        float v3 = oacc[j][3] * inv1;
        bf16 h0 = __float2bfloat16(v0), h1 = __float2bfloat16(v1);
        bf16 h2 = __float2bfloat16(v2), h3 = __float2bfloat16(v3);
        __nv_bfloat162 hp0; hp0.x = h0; hp0.y = h1;
        __nv_bfloat162 hp1; hp1.x = h2; hp1.y = h3;
        *(__nv_bfloat162*)(g_AH + tok0 + col) = hp0;
        *(__nv_bfloat162*)(g_AH + tok1 + col) = hp1;
        __nv_bfloat162 lp0, lp1;
        lp0.x = __float2bfloat16(v0 - __bfloat162float(h0));
        lp0.y = __float2bfloat16(v1 - __bfloat162float(h1));
        lp1.x = __float2bfloat16(v2 - __bfloat162float(h2));
        lp1.y = __float2bfloat16(v3 - __bfloat162float(h3));
        *(__nv_bfloat162*)(g_AL + tok0 + col) = lp0;
        *(__nv_bfloat162*)(g_AL + tok1 + col) = lp1;
    }
}

// ---------------------------------------------------------------------------
extern "C" void kernel_launch(void* const* d_in, const int* in_sizes, int n_in,
                              void* d_out, int out_size)
{
    const float* x  = (const float*)d_in[0];
    const float* Wq = (const float*)d_in[1];
    const float* Wk = (const float*)d_in[2];
    const float* Wv = (const float*)d_in[3];
    const float* Wo = (const float*)d_in[4];
    float* out = (float*)d_out;

    bf16 *XH, *XL, *WTH, *WTL, *QH, *QL, *KH, *KL, *VH, *VL, *AH, *AL;
    cudaGetSymbolAddress((void**)&XH, g_XH);
    cudaGetSymbolAddress((void**)&XL, g_XL);
    cudaGetSymbolAddress((void**)&WTH, g_WTH);
    cudaGetSymbolAddress((void**)&WTL, g_WTL);
    cudaGetSymbolAddress((void**)&QH, g_QH);
    cudaGetSymbolAddress((void**)&QL, g_QL);
    cudaGetSymbolAddress((void**)&KH, g_KH);
    cudaGetSymbolAddress((void**)&KL, g_KL);
    cudaGetSymbolAddress((void**)&VH, g_VH);
    cudaGetSymbolAddress((void**)&VL, g_VL);
    cudaGetSymbolAddress((void**)&AH, g_AH);
    cudaGetSymbolAddress((void**)&AL, g_AL);

    cudaFuncSetAttribute(gemm_mma<true>,
                         cudaFuncAttributeMaxDynamicSharedMemorySize, GSMEM);
    cudaFuncSetAttribute(gemm_mma<false>,
                         cudaFuncAttributeMaxDynamicSharedMemorySize, GSMEM);
    cudaFuncSetAttribute(flash_mma,
                         cudaFuncAttributeMaxDynamicSharedMemorySize, FSMEM);

    dim3 tb(32, 8), tg(DD / 32, DD / 32);
    wtrans<<<tg, tb>>>(Wq, WTH + 0,                WTL + 0);
    wtrans<<<tg, tb>>>(Wk, WTH + 1*(size_t)DD*DD,  WTL + 1*(size_t)DD*DD);
    wtrans<<<tg, tb>>>(Wv, WTH + 2*(size_t)DD*DD,  WTL + 2*(size_t)DD*DD);
    wtrans<<<tg, tb>>>(Wo, WTH + 3*(size_t)DD*DD,  WTL + 3*(size_t)DD*DD);

    const int n4 = MM * DD / 4;
    fsplit<<<n4 / 256, 256>>>(x, XH, XL, n4);

    dim3 gg(DD / 128, MM / 128);   // (8, 32)
    gemm_mma<true><<<gg, 256, GSMEM>>>(XH, XL, WTH + 0,               WTL + 0,               nullptr, QH, QL);
    gemm_mma<true><<<gg, 256, GSMEM>>>(XH, XL, WTH + 1*(size_t)DD*DD, WTL + 1*(size_t)DD*DD, nullptr, KH, KL);
    gemm_mma<true><<<gg, 256, GSMEM>>>(XH, XL, WTH + 2*(size_t)DD*DD, WTL + 2*(size_t)DD*DD, nullptr, VH, VL);

    vtrans<<<dim3(DD/32, SS/32, BB), tb>>>();

    flash_mma<<<dim3(BB*HH, SS/64), 128, FSMEM>>>();

    gemm_mma<false><<<gg, 256, GSMEM>>>(AH, AL, WTH + 3*(size_t)DD*DD, WTL + 3*(size_t)DD*DD, out, nullptr, nullptr);
}

// round 10
// speedup vs baseline: 3.4620x; 1.1111x over previous
#include <cuda_runtime.h>
#include <cuda_bf16.h>
#include <math.h>
#include <stdint.h>

#define BB 2
#define SS 2048
#define DD 1024
#define HH 16
#define DK 64
#define MM (BB*SS)   // 4096 rows

typedef __nv_bfloat16 bf16;

// ---------------------------------------------------------------------------
// Device-global scratch (allocation-free)
// ---------------------------------------------------------------------------
__device__ bf16 g_XH[MM*DD];
__device__ bf16 g_XL[MM*DD];
__device__ bf16 g_WTH[4*DD*DD];    // transposed weights hi [n][k]
__device__ bf16 g_WTL[4*DD*DD];    // transposed weights lo [n][k]
__device__ bf16 g_QH[MM*DD];
__device__ bf16 g_QL[MM*DD];
__device__ bf16 g_KH[MM*DD];
__device__ bf16 g_KL[MM*DD];
__device__ bf16 g_VH[MM*DD];
__device__ bf16 g_VL[MM*DD];
__device__ bf16 g_VTH[MM*DD];      // [b][d][s]
__device__ bf16 g_VTL[MM*DD];
__device__ bf16 g_AH[MM*DD];       // attention out hi/lo
__device__ bf16 g_AL[MM*DD];

__device__ __forceinline__ uint32_t smem_u32(const void* p) {
    uint32_t a;
    asm("{ .reg .u64 t; cvta.to.shared.u64 t, %1; cvt.u32.u64 %0, t; }"
        : "=r"(a) : "l"(p));
    return a;
}

__device__ __forceinline__ void ldsm_x4(uint32_t* r, uint32_t addr) {
    asm volatile("ldmatrix.sync.aligned.m8n8.x4.shared.b16 {%0,%1,%2,%3}, [%4];"
                 : "=r"(r[0]), "=r"(r[1]), "=r"(r[2]), "=r"(r[3]) : "r"(addr));
}

__device__ __forceinline__ void mma16816(float* d, const uint32_t* a,
                                         uint32_t b0, uint32_t b1) {
    asm volatile(
        "mma.sync.aligned.m16n8k16.row.col.f32.bf16.bf16.f32 "
        "{%0,%1,%2,%3}, {%4,%5,%6,%7}, {%8,%9}, {%0,%1,%2,%3};"
        : "+f"(d[0]), "+f"(d[1]), "+f"(d[2]), "+f"(d[3])
        : "r"(a[0]), "r"(a[1]), "r"(a[2]), "r"(a[3]), "r"(b0), "r"(b1));
}

__device__ __forceinline__ uint32_t cvt2(float lo, float hi) {
    uint32_t r;
    asm("cvt.rn.bf16x2.f32 %0, %1, %2;" : "=r"(r) : "f"(hi), "f"(lo));
    return r;
}

// pack high 16 bits of two fp32 (bf16 truncation) into one b32
__device__ __forceinline__ uint32_t hipack(float f0, float f1) {
    uint32_t r;
    asm("prmt.b32 %0, %1, %2, 0x7632;" : "=r"(r)
        : "r"(__float_as_uint(f0)), "r"(__float_as_uint(f1)));
    return r;
}
__device__ __forceinline__ float hitrunc(float f) {
    return __uint_as_float(__float_as_uint(f) & 0xFFFF0000u);
}

__device__ __forceinline__ void cpa16(uint32_t s, const void* g) {
    asm volatile("cp.async.cg.shared.global [%0], [%1], 16;" :: "r"(s), "l"(g));
}
__device__ __forceinline__ void cpcommit() {
    asm volatile("cp.async.commit_group;");
}
template<int N> __device__ __forceinline__ void cpwait() {
    asm volatile("cp.async.wait_group %0;" :: "n"(N));
}

// ---------------------------------------------------------------------------
// fp32 -> bf16 hi/lo split
// ---------------------------------------------------------------------------
__global__ __launch_bounds__(256) void fsplit(
    const float* __restrict__ src, bf16* __restrict__ h, bf16* __restrict__ l, int n4)
{
    int i = blockIdx.x * 256 + threadIdx.x;
    if (i >= n4) return;
    float4 v = ((const float4*)src)[i];
    bf16 h0 = __float2bfloat16(v.x);
    bf16 h1 = __float2bfloat16(v.y);
    bf16 h2 = __float2bfloat16(v.z);
    bf16 h3 = __float2bfloat16(v.w);
    __nv_bfloat162 hh0; hh0.x = h0; hh0.y = h1;
    __nv_bfloat162 hh1; hh1.x = h2; hh1.y = h3;
    ((__nv_bfloat162*)h)[i*2]   = hh0;
    ((__nv_bfloat162*)h)[i*2+1] = hh1;
    __nv_bfloat162 ll0, ll1;
    ll0.x = __float2bfloat16(v.x - __bfloat162float(h0));
    ll0.y = __float2bfloat16(v.y - __bfloat162float(h1));
    ll1.x = __float2bfloat16(v.z - __bfloat162float(h2));
    ll1.y = __float2bfloat16(v.w - __bfloat162float(h3));
    ((__nv_bfloat162*)l)[i*2]   = ll0;
    ((__nv_bfloat162*)l)[i*2+1] = ll1;
}

// ---------------------------------------------------------------------------
// Weight transpose + split, all 4 weights in one launch (z selects W)
// ---------------------------------------------------------------------------
__global__ __launch_bounds__(256) void wtrans4(
    const float* __restrict__ W0, const float* __restrict__ W1,
    const float* __restrict__ W2, const float* __restrict__ W3)
{
    __shared__ float t[32][33];
    const int z = blockIdx.z;
    const float* W = (z == 0) ? W0 : (z == 1) ? W1 : (z == 2) ? W2 : W3;
    bf16* Th = g_WTH + (size_t)z * DD * DD;
    bf16* Tl = g_WTL + (size_t)z * DD * DD;

    const int tx = threadIdx.x, ty = threadIdx.y;   // (32, 8)
    const int bx = blockIdx.x * 32, by = blockIdx.y * 32;
#pragma unroll
    for (int i = 0; i < 4; i++)
        t[ty + i*8][tx] = W[(size_t)(by + ty + i*8) * DD + bx + tx];
    __syncthreads();
#pragma unroll
    for (int i = 0; i < 4; i++) {
        float v = t[tx][ty + i*8];
        size_t o = (size_t)(bx + ty + i*8) * DD + by + tx;
        bf16 h = __float2bfloat16(v);
        Th[o] = h;
        Tl[o] = __float2bfloat16(v - __bfloat162float(h));
    }
}

// ---------------------------------------------------------------------------
// bf16 transpose: V[b*S+s][d] -> VT[(b*D+d)][s]
// ---------------------------------------------------------------------------
__global__ __launch_bounds__(256) void vtrans()
{
    __shared__ bf16 th[32][34];
    __shared__ bf16 tl[32][34];
    const int tx = threadIdx.x, ty = threadIdx.y;
    const int d0 = blockIdx.x * 32;
    const int s0 = blockIdx.y * 32;
    const int b  = blockIdx.z;
#pragma unroll
    for (int i = 0; i < 4; i++) {
        const size_t g = (size_t)(b*SS + s0 + ty + i*8) * DD + d0 + tx;
        th[ty + i*8][tx] = g_VH[g];
        tl[ty + i*8][tx] = g_VL[g];
    }
    __syncthreads();
#pragma unroll
    for (int i = 0; i < 4; i++) {
        const size_t g = (size_t)(b*DD + d0 + ty + i*8) * SS + s0 + tx;
        g_VTH[g] = th[tx][ty + i*8];
        g_VTL[g] = tl[tx][ty + i*8];
    }
}

// ---------------------------------------------------------------------------
// bf16x3 GEMM core, cp.async 2-stage pipeline. CTA 128x128, K-chunk 32.
// SMEM tile: 128x32 bf16 packed as 64 rows x 128B, XOR-swizzled.
// 12 LDSM per k-step: a_hi+b_hi -> term1; b_lo -> term2 (ah*bl);
// a_lo overwrites a -> term3 (al*bh).
// ---------------------------------------------------------------------------
#define G_STG 32768
#define T_AH 0
#define T_AL 8192
#define T_BH 16384
#define T_BL 24576
#define GSMEM (2*G_STG)

__device__ __forceinline__ uint32_t toff(int r, int c) {
    const int pr = r & 63;
    const int pc = c + ((r >> 6) << 2);
    return (uint32_t)(pr * 128 + ((pc ^ (pr & 7)) * 16));
}

template<bool BF16OUT>
__device__ __forceinline__ void gemm_core(
    const bf16* __restrict__ Ah, const bf16* __restrict__ Al,
    const bf16* __restrict__ Bh, const bf16* __restrict__ Bl,
    float* __restrict__ C, bf16* __restrict__ CH, bf16* __restrict__ CL,
    char* sm, int m0, int n0)
{
    const uint32_t sb = smem_u32(sm);
    const int tid  = threadIdx.x;
    const int wid  = tid >> 5;
    const int lane = tid & 31;
    const int wm = (wid & 1) * 64;
    const int wn = (wid >> 1) * 32;

    float acc[4][4][4];
#pragma unroll
    for (int i = 0; i < 4; i++)
#pragma unroll
        for (int j = 0; j < 4; j++)
#pragma unroll
            for (int k = 0; k < 4; k++) acc[i][j][k] = 0.f;

    const int lr = tid >> 1;
    const int cb = (tid & 1) * 2;
    const uint32_t so0 = toff(lr, cb);
    const uint32_t so1 = toff(lr, cb + 1);
    const bf16* pAh = Ah + (size_t)(m0 + lr) * DD + cb * 8;
    const bf16* pAl = Al + (size_t)(m0 + lr) * DD + cb * 8;
    const bf16* pBh = Bh + (size_t)(n0 + lr) * DD + cb * 8;
    const bf16* pBl = Bl + (size_t)(n0 + lr) * DD + cb * 8;

    const int lrow16 = lane & 15;
    const int lhi    = lane >> 4;

#define G_ISSUE(kc, st)                                                        \
    do {                                                                       \
        const int _k0 = (kc) * 32;                                             \
        const uint32_t _s = sb + (st) * G_STG;                                 \
        cpa16(_s + T_AH + so0, pAh + _k0);                                     \
        cpa16(_s + T_AH + so1, pAh + _k0 + 8);                                 \
        cpa16(_s + T_AL + so0, pAl + _k0);                                     \
        cpa16(_s + T_AL + so1, pAl + _k0 + 8);                                 \
        cpa16(_s + T_BH + so0, pBh + _k0);                                     \
        cpa16(_s + T_BH + so1, pBh + _k0 + 8);                                 \
        cpa16(_s + T_BL + so0, pBl + _k0);                                     \
        cpa16(_s + T_BL + so1, pBl + _k0 + 8);                                 \
    } while (0)

    G_ISSUE(0, 0);
    cpcommit();

    for (int kc = 0; kc < 32; kc++) {
        if (kc < 31) {
            G_ISSUE(kc + 1, (kc + 1) & 1);
            cpcommit();
            cpwait<1>();
        } else {
            cpwait<0>();
        }
        __syncthreads();

        const uint32_t st = sb + (kc & 1) * G_STG;
#pragma unroll
        for (int ks = 0; ks < 2; ks++) {
            const int ch = ks * 2 + lhi;

            uint32_t aaddr[4], baddr[2];
#pragma unroll
            for (int mt = 0; mt < 4; mt++)
                aaddr[mt] = st + toff(wm + mt * 16 + lrow16, ch);
#pragma unroll
            for (int nt = 0; nt < 2; nt++)
                baddr[nt] = st + toff(wn + nt * 16 + lrow16, ch);

            uint32_t a[4][4], bh_[2][4], bl_[2][4];

            // term1: ah * bh
#pragma unroll
            for (int mt = 0; mt < 4; mt++) ldsm_x4(a[mt], aaddr[mt] + T_AH);
#pragma unroll
            for (int nt = 0; nt < 2; nt++) ldsm_x4(bh_[nt], baddr[nt] + T_BH);
#pragma unroll
            for (int mt = 0; mt < 4; mt++)
#pragma unroll
                for (int nt = 0; nt < 4; nt++)
                    mma16816(acc[mt][nt], a[mt],
                             bh_[nt >> 1][nt & 1], bh_[nt >> 1][(nt & 1) + 2]);

            // term2: ah * bl (reuse a)
#pragma unroll
            for (int nt = 0; nt < 2; nt++) ldsm_x4(bl_[nt], baddr[nt] + T_BL);
#pragma unroll
            for (int mt = 0; mt < 4; mt++)
#pragma unroll
                for (int nt = 0; nt < 4; nt++)
                    mma16816(acc[mt][nt], a[mt],
                             bl_[nt >> 1][nt & 1], bl_[nt >> 1][(nt & 1) + 2]);

            // term3: al * bh (reuse bh_, overwrite a)
#pragma unroll
            for (int mt = 0; mt < 4; mt++) ldsm_x4(a[mt], aaddr[mt] + T_AL);
#pragma unroll
            for (int mt = 0; mt < 4; mt++)
#pragma unroll
                for (int nt = 0; nt < 4; nt++)
                    mma16816(acc[mt][nt], a[mt],
                             bh_[nt >> 1][nt & 1], bh_[nt >> 1][(nt & 1) + 2]);
        }
        __syncthreads();
    }
#undef G_ISSUE

    const int er = lane >> 2;
    const int ec = (lane & 3) * 2;
#pragma unroll
    for (int mt = 0; mt < 4; mt++) {
#pragma unroll
        for (int nt = 0; nt < 4; nt++) {
            const size_t o0 = (size_t)(m0 + wm + mt*16 + er) * DD + n0 + wn + nt*8 + ec;
            const size_t o1 = o0 + 8 * DD;
            if (BF16OUT) {
                float v0 = acc[mt][nt][0], v1 = acc[mt][nt][1];
                float v2 = acc[mt][nt][2], v3 = acc[mt][nt][3];
                bf16 h0 = __float2bfloat16(v0), h1 = __float2bfloat16(v1);
                bf16 h2 = __float2bfloat16(v2), h3 = __float2bfloat16(v3);
                __nv_bfloat162 hp0; hp0.x = h0; hp0.y = h1;
                __nv_bfloat162 hp1; hp1.x = h2; hp1.y = h3;
                *(__nv_bfloat162*)(CH + o0) = hp0;
                *(__nv_bfloat162*)(CH + o1) = hp1;
                __nv_bfloat162 lp0, lp1;
                lp0.x = __float2bfloat16(v0 - __bfloat162float(h0));
                lp0.y = __float2bfloat16(v1 - __bfloat162float(h1));
                lp1.x = __float2bfloat16(v2 - __bfloat162float(h2));
                lp1.y = __float2bfloat16(v3 - __bfloat162float(h3));
                *(__nv_bfloat162*)(CL + o0) = lp0;
                *(__nv_bfloat162*)(CL + o1) = lp1;
            } else {
                float2 v0; v0.x = acc[mt][nt][0]; v0.y = acc[mt][nt][1];
                float2 v1; v1.x = acc[mt][nt][2]; v1.y = acc[mt][nt][3];
                *(float2*)(C + o0) = v0;
                *(float2*)(C + o1) = v1;
            }
        }
    }
}

// Q/K/V projections in one launch: grid (8, 32, 3)
__global__ __launch_bounds__(256) void gemm_qkv()
{
    extern __shared__ char sm[];
    const int z = blockIdx.z;
    const bf16* Bh = g_WTH + (size_t)z * DD * DD;
    const bf16* Bl = g_WTL + (size_t)z * DD * DD;
    bf16* CH = (z == 0) ? g_QH : (z == 1) ? g_KH : g_VH;
    bf16* CL = (z == 0) ? g_QL : (z == 1) ? g_KL : g_VL;
    gemm_core<true>(g_XH, g_XL, Bh, Bl, nullptr, CH, CL,
                    sm, blockIdx.y * 128, blockIdx.x * 128);
}

// O projection: fp32 output to d_out
__global__ __launch_bounds__(256) void gemm_o(float* __restrict__ C)
{
    extern __shared__ char sm[];
    gemm_core<false>(g_AH, g_AL,
                     g_WTH + 3*(size_t)DD*DD, g_WTL + 3*(size_t)DD*DD,
                     C, nullptr, nullptr,
                     sm, blockIdx.y * 128, blockIdx.x * 128);
}

// ---------------------------------------------------------------------------
// Tensor-core causal flash attention, cp.async 2-stage K/V pipeline.
// CTA: 128 threads, 64 queries x DK=64. Heavy CTAs (large qb) first.
// ---------------------------------------------------------------------------
#define F_STG 32768
#define FS_KH 0
#define FS_KL 8192
#define FS_VH 16384
#define FS_VL 24576
#define FSMEM (2*F_STG)

__global__ __launch_bounds__(128) void flash_mma()
{
    extern __shared__ char fsm[];
    const uint32_t sb = smem_u32(fsm);

    const int tid  = threadIdx.x;
    const int w    = tid >> 5;
    const int lane = tid & 31;
    const int bh = blockIdx.x;
    const int b  = bh >> 4;
    const int h  = bh & 15;
    const int qb = (int)gridDim.y - 1 - (int)blockIdx.y;   // heavy first

    const int lrow16 = lane & 15;
    const int lhi    = lane >> 4;

    // ---- stage Q tile (64x64 hi+lo) ----
    {
        const bf16* QHg = g_QH + (size_t)(b*SS + qb*64) * DD + h*64;
        const bf16* QLg = g_QL + (size_t)(b*SS + qb*64) * DD + h*64;
#pragma unroll
        for (int i = 0; i < 4; i++) {
            const int idx = tid + i*128;
            const int r = idx >> 3, c = idx & 7;
            const uint32_t so = r * 128 + ((c ^ (r & 7)) * 16);
            *(float4*)(fsm + FS_KH + so) = *(const float4*)(QHg + (size_t)r*DD + c*8);
            *(float4*)(fsm + FS_KL + so) = *(const float4*)(QLg + (size_t)r*DD + c*8);
        }
    }
    __syncthreads();

    uint32_t qh[4][4], ql[4][4];
#pragma unroll
    for (int kk = 0; kk < 4; kk++) {
        const int r = w*16 + lrow16;
        const int ch = kk*2 + lhi;
        const uint32_t ao = r * 128 + ((ch ^ (r & 7)) * 16);
        ldsm_x4(qh[kk], sb + FS_KH + ao);
        ldsm_x4(ql[kk], sb + FS_KL + ao);
    }
    __syncthreads();

    const int vr = tid >> 3;
    const int vc = tid & 7;
    const bf16* KHg  = g_KH  + (size_t)(b*SS) * DD + h*64;
    const bf16* KLg  = g_KL  + (size_t)(b*SS) * DD + h*64;
    const bf16* VTHg = g_VTH + (size_t)(b*DD + h*64) * SS;
    const bf16* VTLg = g_VTL + (size_t)(b*DD + h*64) * SS;

#define F_ISSUE(kb, st)                                                        \
    do {                                                                       \
        const uint32_t _s = sb + (st) * F_STG;                                 \
        const int _k0 = (kb) * 64;                                             \
        _Pragma("unroll")                                                      \
        for (int i = 0; i < 4; i++) {                                          \
            const int r = vr + i * 16;                                         \
            const uint32_t so = r * 128 + ((vc ^ (r & 7)) * 16);               \
            cpa16(_s + FS_KH + so, KHg  + (size_t)(_k0 + r)*DD + vc*8);        \
            cpa16(_s + FS_KL + so, KLg  + (size_t)(_k0 + r)*DD + vc*8);        \
            cpa16(_s + FS_VH + so, VTHg + (size_t)r*SS + _k0 + vc*8);          \
            cpa16(_s + FS_VL + so, VTLg + (size_t)r*SS + _k0 + vc*8);          \
        }                                                                      \
    } while (0)

    F_ISSUE(0, 0);
    cpcommit();

    float oacc[8][4];
#pragma unroll
    for (int j = 0; j < 8; j++)
#pragma unroll
        for (int e = 0; e < 4; e++) oacc[j][e] = 0.f;
    float l0 = 0.f, l1 = 0.f;

    const int rloc = w*16 + (lane >> 2);
    const int grow = qb*64 + rloc;
    const int ecol = (lane & 3) * 2;

    for (int kb = 0; kb <= qb; kb++) {
        if (kb < qb) {
            F_ISSUE(kb + 1, (kb + 1) & 1);
            cpcommit();
            cpwait<1>();
        } else {
            cpwait<0>();
        }
        __syncthreads();

        const uint32_t st = sb + (kb & 1) * F_STG;

        // ---- S = Q K^T (bf16x3) ----
        float sacc[8][4];
#pragma unroll
        for (int j = 0; j < 8; j++)
#pragma unroll
            for (int e = 0; e < 4; e++) sacc[j][e] = 0.f;

#pragma unroll
        for (int kk = 0; kk < 4; kk++) {
            const int ch = kk*2 + lhi;
#pragma unroll
            for (int nb = 0; nb < 4; nb++) {
                const int r = nb*16 + lrow16;
                const uint32_t ao = r * 128 + ((ch ^ (r & 7)) * 16);
                uint32_t bhf[4], blf[4];
                ldsm_x4(bhf, st + FS_KH + ao);
                ldsm_x4(blf, st + FS_KL + ao);
#pragma unroll
                for (int nt = 0; nt < 2; nt++) {
                    float* s = sacc[nb*2 + nt];
                    mma16816(s, qh[kk], bhf[nt], bhf[nt + 2]);
                    mma16816(s, qh[kk], blf[nt], blf[nt + 2]);
                    mma16816(s, ql[kk], bhf[nt], bhf[nt + 2]);
                }
            }
        }

        // ---- softmax (no-max): p = exp(s/8), causal masked ----
        if (kb == qb) {
#pragma unroll
            for (int j = 0; j < 8; j++) {
#pragma unroll
                for (int e = 0; e < 4; e++) {
                    const int col = kb*64 + j*8 + ecol + (e & 1);
                    const int row = grow + ((e >> 1) * 8);
                    float p = (col <= row) ? __expf(sacc[j][e] * 0.125f) : 0.f;
                    sacc[j][e] = p;
                    if (e < 2) l0 += p; else l1 += p;
                }
            }
        } else {
#pragma unroll
            for (int j = 0; j < 8; j++) {
#pragma unroll
                for (int e = 0; e < 4; e++) {
                    float p = __expf(sacc[j][e] * 0.125f);
                    sacc[j][e] = p;
                    if (e < 2) l0 += p; else l1 += p;
                }
            }
        }

        // ---- O += P V (bf16x3), truncation-based P split ----
#pragma unroll
        for (int kk = 0; kk < 4; kk++) {
            uint32_t pah[4], pal[4];
            {
                const float* s0 = sacc[kk*2];
                const float* s1 = sacc[kk*2 + 1];
                pah[0] = hipack(s0[0], s0[1]);
                pah[1] = hipack(s0[2], s0[3]);
                pah[2] = hipack(s1[0], s1[1]);
                pah[3] = hipack(s1[2], s1[3]);
                pal[0] = cvt2(s0[0] - hitrunc(s0[0]), s0[1] - hitrunc(s0[1]));
                pal[1] = cvt2(s0[2] - hitrunc(s0[2]), s0[3] - hitrunc(s0[3]));
                pal[2] = cvt2(s1[0] - hitrunc(s1[0]), s1[1] - hitrunc(s1[1]));
                pal[3] = cvt2(s1[2] - hitrunc(s1[2]), s1[3] - hitrunc(s1[3]));
            }
            const int ch = kk*2 + lhi;
#pragma unroll
            for (int db = 0; db < 4; db++) {
                const int r = db*16 + lrow16;
                const uint32_t ao = r * 128 + ((ch ^ (r & 7)) * 16);
                uint32_t vhf[4], vlf[4];
                ldsm_x4(vhf, st + FS_VH + ao);
                ldsm_x4(vlf, st + FS_VL + ao);
#pragma unroll
                for (int nt = 0; nt < 2; nt++) {
                    float* o = oacc[db*2 + nt];
                    mma16816(o, pah, vhf[nt], vhf[nt + 2]);
                    mma16816(o, pal, vhf[nt], vhf[nt + 2]);
                    mma16816(o, pah, vlf[nt], vlf[nt + 2]);
                }
            }
        }
        __syncthreads();
    }
#undef F_ISSUE

    l0 += __shfl_xor_sync(0xFFFFFFFFu, l0, 1);
    l0 += __shfl_xor_sync(0xFFFFFFFFu, l0, 2);
    l1 += __shfl_xor_sync(0xFFFFFFFFu, l1, 1);
    l1 += __shfl_xor_sync(0xFFFFFFFFu, l1, 2);
    const float inv0 = 1.f / l0;
    const float inv1 = 1.f / l1;

    const size_t tok0 = (size_t)(b*SS + grow) * DD + h*64;
    const size_t tok1 = tok0 + 8 * DD;
#pragma unroll
    for (int j = 0; j < 8; j++) {
        const int col = j*8 + ecol;
        float v0 = oacc[j][0] * inv0;
        float v1 = oacc[j][1] * inv0;
        float v2 = oacc[j][2] * inv1;
        float v3 = oacc[j][3] * inv1;
        bf16 h0 = __float2bfloat16(v0), h1 = __float2bfloat16(v1);
        bf16 h2 = __float2bfloat16(v2), h3 = __float2bfloat16(v3);
        __nv_bfloat162 hp0; hp0.x = h0; hp0.y = h1;
        __nv_bfloat162 hp1; hp1.x = h2; hp1.y = h3;
        *(__nv_bfloat162*)(g_AH + tok0 + col) = hp0;
        *(__nv_bfloat162*)(g_AH + tok1 + col) = hp1;
        __nv_bfloat162 lp0, lp1;
        lp0.x = __float2bfloat16(v0 - __bfloat162float(h0));
        lp0.y = __float2bfloat16(v1 - __bfloat162float(h1));
        lp1.x = __float2bfloat16(v2 - __bfloat162float(h2));
        lp1.y = __float2bfloat16(v3 - __bfloat162float(h3));
        *(__nv_bfloat162*)(g_AL + tok0 + col) = lp0;
        *(__nv_bfloat162*)(g_AL + tok1 + col) = lp1;
    }
}

// ---------------------------------------------------------------------------
extern "C" void kernel_launch(void* const* d_in, const int* in_sizes, int n_in,
                              void* d_out, int out_size)
{
    const float* x  = (const float*)d_in[0];
    const float* Wq = (const float*)d_in[1];
    const float* Wk = (const float*)d_in[2];
    const float* Wv = (const float*)d_in[3];
    const float* Wo = (const float*)d_in[4];
    float* out = (float*)d_out;

    bf16 *XH, *XL;
    cudaGetSymbolAddress((void**)&XH, g_XH);
    cudaGetSymbolAddress((void**)&XL, g_XL);

    cudaFuncSetAttribute(gemm_qkv,
                         cudaFuncAttributeMaxDynamicSharedMemorySize, GSMEM);
    cudaFuncSetAttribute(gemm_o,
                         cudaFuncAttributeMaxDynamicSharedMemorySize, GSMEM);
    cudaFuncSetAttribute(flash_mma,
                         cudaFuncAttributeMaxDynamicSharedMemorySize, FSMEM);

    dim3 tb(32, 8);
    wtrans4<<<dim3(DD/32, DD/32, 4), tb>>>(Wq, Wk, Wv, Wo);

    const int n4 = MM * DD / 4;
    fsplit<<<n4 / 256, 256>>>(x, XH, XL, n4);

    gemm_qkv<<<dim3(DD/128, MM/128, 3), 256, GSMEM>>>();

    vtrans<<<dim3(DD/32, SS/32, BB), tb>>>();

    flash_mma<<<dim3(BB*HH, SS/64), 128, FSMEM>>>();

    gemm_o<<<dim3(DD/128, MM/128), 256, GSMEM>>>(out);
}